// round 13
// baseline (speedup 1.0000x reference)
#include <cuda_runtime.h>
#include <cuda_bf16.h>
#include <math.h>

typedef unsigned long long u64;

#define NB 8
#define NM 4
#define NT 2048
#define NE 768
#define NP 256
#define NH 128
#define NX 16
#define NCOMB 384
#define NMLP 192
#define NKD 64
#define NVD 64
#define NTOK (NB*NM*NT)   /* 65536 */

// ---------------- scratch ----------------------------------------------------
__device__ float g_processed[(size_t)NTOK*NP];
__device__ float g_hid[(size_t)NTOK*NMLP];
__device__ float g_scal[(size_t)NTOK*2];
__device__ float g_rus[(size_t)NTOK*NH];
__device__ float g_wa[NP], g_wb[NP], g_wc[NP];
__device__ float g_cc[3];
__device__ float g_c0[3*NH], g_c1[3*NH], g_c2[3*NH], g_c3[3*NH];
__device__ __nv_bfloat16 g_wthi[NP*NE], g_wtlo[NP*NE];
__device__ __nv_bfloat16 g_w1hi[NMLP*NCOMB], g_w1lo[NMLP*NCOMB];

// ---------------- f32x2 helpers (GRU) ---------------------------------------
__device__ __forceinline__ u64 ffma2(u64 a, u64 b, u64 c) {
    u64 d;
    asm("fma.rn.f32x2 %0, %1, %2, %3;" : "=l"(d) : "l"(a), "l"(b), "l"(c));
    return d;
}
__device__ __forceinline__ float lo2(u64 v) { return __uint_as_float((unsigned)v); }
__device__ __forceinline__ float hi2(u64 v) { return __uint_as_float((unsigned)(v >> 32)); }
__device__ __forceinline__ float sigf(float x) {
    return __fdividef(1.f, 1.f + __expf(-x));
}

// ---------------- mma helpers ------------------------------------------------
__device__ __forceinline__ unsigned smem_u32(const void* p) {
    unsigned a;
    asm("{ .reg .u64 t; cvta.to.shared.u64 t, %1; cvt.u32.u64 %0, t; }"
        : "=r"(a) : "l"(p));
    return a;
}
__device__ __forceinline__ void ldsm4(unsigned& r0, unsigned& r1,
                                      unsigned& r2, unsigned& r3, unsigned addr) {
    asm volatile("ldmatrix.sync.aligned.m8n8.x4.shared.b16 {%0,%1,%2,%3}, [%4];"
                 : "=r"(r0), "=r"(r1), "=r"(r2), "=r"(r3) : "r"(addr));
}
__device__ __forceinline__ void mma16816(float* c, const unsigned* a,
                                         unsigned b0, unsigned b1) {
    asm volatile(
        "mma.sync.aligned.m16n8k16.row.col.f32.bf16.bf16.f32 "
        "{%0,%1,%2,%3}, {%4,%5,%6,%7}, {%8,%9}, {%0,%1,%2,%3};"
        : "+f"(c[0]), "+f"(c[1]), "+f"(c[2]), "+f"(c[3])
        : "r"(a[0]), "r"(a[1]), "r"(a[2]), "r"(a[3]), "r"(b0), "r"(b1));
}
__device__ __forceinline__ void cpasync16(unsigned dst, const void* src) {
    asm volatile("cp.async.ca.shared.global [%0], [%1], 16;"
                 :: "r"(dst), "l"(src) : "memory");
}
#define SW128(x) ((x) ^ (((x) >> 3) & 0x70))

// ---------------- precompute folded weight vectors ---------------------------
__global__ void __launch_bounds__(384) k_pre(
                      const float* __restrict__ qw, const float* __restrict__ qb,
                      const float* __restrict__ kw, const float* __restrict__ kb,
                      const float* __restrict__ wih, const float* __restrict__ bih,
                      const float* __restrict__ vw, const float* __restrict__ vb) {
    int i = threadIdx.x;
    if (i < NP) {
        float a = 0.f, b = 0.f, c = 0.f;
#pragma unroll 4
        for (int k = 0; k < NKD; k++) {
            float q = qw[k*NP + i];
            a = fmaf(q, kw[2*k], a);
            b = fmaf(q, kw[2*k+1], b);
            c = fmaf(q, kb[k], c);
        }
        g_wa[i] = a; g_wb[i] = b; g_wc[i] = c;
    }
    if (i == 0) {
        float a = 0.f, b = 0.f, c = 0.f;
#pragma unroll 4
        for (int k = 0; k < NKD; k++) {
            float q = qb[k];
            a = fmaf(q, kw[2*k], a);
            b = fmaf(q, kw[2*k+1], b);
            c = fmaf(q, kb[k], c);
        }
        g_cc[0] = a; g_cc[1] = b; g_cc[2] = c;
    }
    if (i < 3*NH) {
        const float* wr = wih + (size_t)i*(1 + NVD);
        float c1 = 0.f, c2 = 0.f, c3 = bih[i];
#pragma unroll 4
        for (int v = 0; v < NVD; v++) {
            float w = wr[1 + v];
            c1 = fmaf(w, vw[2*v], c1);
            c2 = fmaf(w, vw[2*v+1], c2);
            c3 = fmaf(w, vb[v], c3);
        }
        g_c0[i] = wr[0]; g_c1[i] = c1; g_c2[i] = c2; g_c3[i] = c3;
    }
}

// ---------------- fp32 -> bf16 hi/lo split (weights only) --------------------
__global__ void __launch_bounds__(256) k_cvt(const float* __restrict__ src,
                                             __nv_bfloat16* __restrict__ hi,
                                             __nv_bfloat16* __restrict__ lo) {
    size_t i4 = ((size_t)blockIdx.x * 256 + threadIdx.x) * 4;
    float4 v = *(const float4*)&src[i4];
    __nv_bfloat16 h0 = __float2bfloat16(v.x);
    __nv_bfloat16 h1 = __float2bfloat16(v.y);
    __nv_bfloat16 h2 = __float2bfloat16(v.z);
    __nv_bfloat16 h3 = __float2bfloat16(v.w);
    __nv_bfloat16 l0 = __float2bfloat16(v.x - __bfloat162float(h0));
    __nv_bfloat16 l1 = __float2bfloat16(v.y - __bfloat162float(h1));
    __nv_bfloat16 l2 = __float2bfloat16(v.z - __bfloat162float(h2));
    __nv_bfloat16 l3 = __float2bfloat16(v.w - __bfloat162float(h3));
    __nv_bfloat162* hp = (__nv_bfloat162*)&hi[i4];
    __nv_bfloat162* lp = (__nv_bfloat162*)&lo[i4];
    hp[0] = __nv_bfloat162(h0, h1); hp[1] = __nv_bfloat162(h2, h3);
    lp[0] = __nv_bfloat162(l0, l1); lp[1] = __nv_bfloat162(l2, l3);
}

// ============================================================================
// Split-bf16 GEMM via mma.sync, f32 A in (hi/lo split fused into the fill):
// C = relu(A @ W^T + bias), ~fp32 accuracy.
// Block tile 128 x TN, k-slab 64, 512 threads (16 warps: 4m x 4n).
// 3 products per k16: ah*bh + ah*bl + al*bh.
// ============================================================================
template<int TN>
__global__ void __launch_bounds__(512) k_mma(
    const float* __restrict__ A1, int lda1, int K1,
    const float* __restrict__ A2, int lda2,
    const __nv_bfloat16* __restrict__ Bh, const __nv_bfloat16* __restrict__ Bl,
    int ldb,
    const float* __restrict__ bias, float* __restrict__ C, int ldc, int K)
{
    constexpr int WN  = TN / 4;
    constexpr int NT8 = WN / 8;
    constexpr int BSTG = TN * 128;

    extern __shared__ char smem[];
    char* sA = smem;                 // 2 stages x (16KB hi + 16KB lo)
    char* sB = smem + 65536;         // 2 stages x (BSTG hi + BSTG lo)

    const int tid = threadIdx.x;
    const int w = tid >> 5, lane = tid & 31;
    const int wm = w & 3, wn = w >> 2;
    const int m0 = blockIdx.y << 7, n0 = blockIdx.x * TN;
    const int gid = lane >> 2, tig = lane & 3;

    float acc[2][NT8][4];
#pragma unroll
    for (int mi = 0; mi < 2; ++mi)
#pragma unroll
        for (int nj = 0; nj < NT8; ++nj)
#pragma unroll
            for (int q = 0; q < 4; ++q) acc[mi][nj][q] = 0.f;

    const int a_row = (lane & 7) + ((lane >> 3) & 1) * 8;
    const int a_kh  = (lane >> 4) * 16;
    const int b_row = (lane & 7) + ((lane >> 4) & 1) * 8;
    const int b_kh  = ((lane >> 3) & 1) * 16;

    const unsigned uA = smem_u32(sA), uB = smem_u32(sB);
    const int nslab = K >> 6;
    constexpr int NBF = (TN * 8) / 512;

    auto fillB = [&](int st, int k0) {
#pragma unroll
        for (int ib = 0; ib < NBF; ++ib) {
            int idx = (ib << 9) + tid;
            int r = idx >> 3, k8 = idx & 7;
            unsigned sw = SW128(r * 128 + (k8 << 4));
            size_t go = (size_t)(n0 + r) * ldb + k0 + (k8 << 3);
            cpasync16(uB + st * (2 * BSTG) + sw, &Bh[go]);
            cpasync16(uB + st * (2 * BSTG) + BSTG + sw, &Bl[go]);
        }
        asm volatile("cp.async.commit_group;" ::: "memory");
    };
    auto loadA = [&](int k0, float4* ra) {
        const float* Asrc; int lda, acol;
        if (k0 < K1) { Asrc = A1; lda = lda1; acol = k0; }
        else         { Asrc = A2; lda = lda2; acol = k0 - K1; }
#pragma unroll
        for (int it = 0; it < 4; ++it) {
            int idx = (it << 9) + tid;
            int r = idx >> 4, c4 = idx & 15;
            ra[it] = *(const float4*)&Asrc[(size_t)(m0 + r) * lda + acol + (c4 << 2)];
        }
    };
    auto storeA = [&](int st, const float4* ra) {
#pragma unroll
        for (int it = 0; it < 4; ++it) {
            int idx = (it << 9) + tid;
            int r = idx >> 4, c4 = idx & 15;
            unsigned sw = SW128(r * 128 + (c4 << 3));
            float4 v = ra[it];
            __nv_bfloat16 h0 = __float2bfloat16(v.x);
            __nv_bfloat16 h1 = __float2bfloat16(v.y);
            __nv_bfloat16 h2 = __float2bfloat16(v.z);
            __nv_bfloat16 h3 = __float2bfloat16(v.w);
            __nv_bfloat162 hp0(h0, h1), hp1(h2, h3);
            __nv_bfloat162 lp0(__float2bfloat16(v.x - __bfloat162float(h0)),
                               __float2bfloat16(v.y - __bfloat162float(h1)));
            __nv_bfloat162 lp1(__float2bfloat16(v.z - __bfloat162float(h2)),
                               __float2bfloat16(v.w - __bfloat162float(h3)));
            char* ph = sA + st * 32768 + sw;
            char* pl = sA + st * 32768 + 16384 + sw;
            ((__nv_bfloat162*)ph)[0] = hp0; ((__nv_bfloat162*)ph)[1] = hp1;
            ((__nv_bfloat162*)pl)[0] = lp0; ((__nv_bfloat162*)pl)[1] = lp1;
        }
    };

    {
        float4 ra[4];
        loadA(0, ra);
        storeA(0, ra);
        fillB(0, 0);
        asm volatile("cp.async.wait_group 0;" ::: "memory");
    }
    __syncthreads();

    for (int s = 0; s < nslab; ++s) {
        const int cur = s & 1;
        const bool more = (s + 1 < nslab);
        float4 ra[4];
        if (more) {
            fillB(cur ^ 1, (s + 1) << 6);
            loadA((s + 1) << 6, ra);
        }
        const unsigned uAh = uA + cur * 32768;
        const unsigned uAl = uAh + 16384;
        const unsigned uBh = uB + cur * (2 * BSTG);
        const unsigned uBl = uBh + BSTG;
#pragma unroll
        for (int j = 0; j < 4; ++j) {
            const int kb = j * 32;
            unsigned ah[2][4], al[2][4], bh[NT8][2], bl[NT8][2];
            unsigned aoff = SW128((wm * 32 + a_row) * 128 + kb + a_kh);
            ldsm4(ah[0][0], ah[0][1], ah[0][2], ah[0][3], uAh + aoff);
            ldsm4(ah[1][0], ah[1][1], ah[1][2], ah[1][3], uAh + aoff + 2048);
            ldsm4(al[0][0], al[0][1], al[0][2], al[0][3], uAl + aoff);
            ldsm4(al[1][0], al[1][1], al[1][2], al[1][3], uAl + aoff + 2048);
            unsigned boff = SW128((wn * WN + b_row) * 128 + kb + b_kh);
#pragma unroll
            for (int g = 0; g < NT8 / 2; ++g) {
                ldsm4(bh[2*g][0], bh[2*g][1], bh[2*g+1][0], bh[2*g+1][1],
                      uBh + boff + g * 2048);
                ldsm4(bl[2*g][0], bl[2*g][1], bl[2*g+1][0], bl[2*g+1][1],
                      uBl + boff + g * 2048);
            }
#pragma unroll
            for (int mi = 0; mi < 2; ++mi)
#pragma unroll
                for (int nj = 0; nj < NT8; ++nj)
                    mma16816(acc[mi][nj], ah[mi], bh[nj][0], bh[nj][1]);
#pragma unroll
            for (int mi = 0; mi < 2; ++mi)
#pragma unroll
                for (int nj = 0; nj < NT8; ++nj)
                    mma16816(acc[mi][nj], ah[mi], bl[nj][0], bl[nj][1]);
#pragma unroll
            for (int mi = 0; mi < 2; ++mi)
#pragma unroll
                for (int nj = 0; nj < NT8; ++nj)
                    mma16816(acc[mi][nj], al[mi], bh[nj][0], bh[nj][1]);
        }
        if (more) {
            storeA(cur ^ 1, ra);
            asm volatile("cp.async.wait_group 0;" ::: "memory");
            __syncthreads();
        }
    }

#pragma unroll
    for (int mi = 0; mi < 2; ++mi) {
#pragma unroll
        for (int half = 0; half < 2; ++half) {
            const int row = m0 + wm * 32 + mi * 16 + gid + half * 8;
#pragma unroll
            for (int nj = 0; nj < NT8; ++nj) {
                const int col = n0 + wn * WN + nj * 8 + tig * 2;
                float2 bv = *(const float2*)&bias[col];
                float v0 = fmaxf(acc[mi][nj][half * 2 + 0] + bv.x, 0.f);
                float v1 = fmaxf(acc[mi][nj][half * 2 + 1] + bv.y, 0.f);
                *(float2*)&C[(size_t)row * ldc + col] = make_float2(v0, v1);
            }
        }
    }
}

// ---------------- per-token attention scalars (Ar, As) ----------------------
__global__ void __launch_bounds__(256) k_scal(const float* __restrict__ R,
                                              const float* __restrict__ S) {
    int warp = (blockIdx.x * blockDim.x + threadIdx.x) >> 5;
    int lane = threadIdx.x & 31;
    if (warp >= NTOK) return;
    int tok = warp;
    const float* pr = g_processed + (size_t)tok * NP;
    float aa = 0.f, ab = 0.f, ac = 0.f;
#pragma unroll
    for (int p = lane; p < NP; p += 32) {
        float pv = pr[p];
        aa = fmaf(pv, g_wa[p], aa);
        ab = fmaf(pv, g_wb[p], ab);
        ac = fmaf(pv, g_wc[p], ac);
    }
#pragma unroll
    for (int o = 16; o; o >>= 1) {
        aa += __shfl_down_sync(0xffffffffu, aa, o);
        ab += __shfl_down_sync(0xffffffffu, ab, o);
        ac += __shfl_down_sync(0xffffffffu, ac, o);
    }
    if (lane == 0) {
        aa += g_cc[0]; ab += g_cc[1]; ac += g_cc[2];
        int t = tok & (NT - 1);
        int s = tok >> 11;          // b*4+m
        int m = s & 3;
        float sc[3], Ro[3], So[3];
        int n = 0;
        for (int j = 0; j < NM; j++) {
            if (j == m) continue;
            size_t idx = ((size_t)s * NM + j) * NT + t;
            float r = R[idx], sv = S[idx];
            Ro[n] = r; So[n] = sv;
            sc[n] = (fmaf(aa, r, fmaf(ab, sv, ac))) * 0.125f;
            n++;
        }
        float mx = fmaxf(sc[0], fmaxf(sc[1], sc[2]));
        float e0 = expf(sc[0] - mx), e1 = expf(sc[1] - mx), e2 = expf(sc[2] - mx);
        float inv = 1.f / (e0 + e1 + e2);
        g_scal[2*tok]   = (e0*Ro[0] + e1*Ro[1] + e2*Ro[2]) * inv;
        g_scal[2*tok+1] = (e0*So[0] + e1*So[1] + e2*So[2]) * inv;
    }
}

// ---------------- GRU scan: one block per sequence (32 blocks) --------------
// Single __syncthreads per step. Each warp keeps a private h copy and
// redundantly computes all 128 hnew in its tail (latency shared across 12
// warps). Gate exchange double-buffered by step parity (removes 2nd barrier).
__global__ void __launch_bounds__(384, 1) k_gru(const float* __restrict__ U,
                                                const float* __restrict__ whh,
                                                const float* __restrict__ bhh) {
    __shared__ __align__(16) float hbufw[12][NH];
    __shared__ float ex_r[2][NH], ex_z[2][NH], ex_hn[2][NH], ex_xn[2][NH];
    __shared__ float su[512], sar[512], sas[512];
    const int s = blockIdx.x;
    const int i = threadIdx.x;
    const int w = i >> 5, lane = i & 31;

    u64 w2r[NH/2];
    const u64* wp = (const u64*)(whh + (size_t)i * NH);
#pragma unroll
    for (int k = 0; k < NH/2; k++) w2r[k] = wp[k];
    const float bb = bhh[i];
    const float c0 = g_c0[i], c1 = g_c1[i], c2 = g_c2[i], c3 = g_c3[i];

#pragma unroll
    for (int q = 0; q < 4; ++q) hbufw[w][lane + (q << 5)] = 0.f;

    const size_t base = (size_t)s * NT;
    float* outp = g_rus + base * NH;

    for (int t0 = 0; t0 < NT; t0 += 512) {
        __syncthreads();
        for (int j = i; j < 512; j += 384) {
            size_t g = base + t0 + j;
            su[j]  = U[g];
            sar[j] = g_scal[2*g];
            sas[j] = g_scal[2*g + 1];
        }
        __syncthreads();
        for (int tt = 0; tt < 512; tt++) {
            const int par = tt & 1;
            float xt = fmaf(su[tt], c0, fmaf(sar[tt], c1, fmaf(sas[tt], c2, c3)));
            u64 a0 = 0ull, a1 = 0ull;
            const float* hb = hbufw[w];
#pragma unroll
            for (int k = 0; k < NH/4; k++) {
                ulonglong2 hv = *(const ulonglong2*)&hb[k << 2];
                a0 = ffma2(w2r[2*k],   hv.x, a0);
                a1 = ffma2(w2r[2*k+1], hv.y, a1);
            }
            float acc = bb + ((lo2(a0) + hi2(a0)) + (lo2(a1) + hi2(a1)));
            if (i < NH)          ex_r[par][i] = sigf(acc + xt);
            else if (i < 2*NH)   ex_z[par][i - NH] = sigf(acc + xt);
            else { ex_hn[par][i - 2*NH] = acc; ex_xn[par][i - 2*NH] = xt; }
            __syncthreads();
            // every warp computes all 128 hnew into its own copy
#pragma unroll
            for (int q = 0; q < 4; ++q) {
                const int j = lane + (q << 5);
                float r  = ex_r[par][j];
                float z  = ex_z[par][j];
                float pre = fmaf(r, ex_hn[par][j], ex_xn[par][j]);
                float nn = fmaf(2.f, sigf(2.f * pre), -1.f);
                float hnew = fmaf(z, hbufw[w][j] - nn, nn);
                hbufw[w][j] = hnew;
                if (w == 0) outp[(size_t)(t0 + tt) * NH + j] = hnew;
            }
            __syncwarp();
        }
    }
}

// ---------------- final 192 -> 16 projection --------------------------------
__global__ void __launch_bounds__(256) k_mlp2(const float* __restrict__ w2,
                                              const float* __restrict__ b2,
                                              float* __restrict__ out) {
    __shared__ __align__(16) float sh[16][196];
    __shared__ __align__(16) float sw[16][196];
    const int tid = threadIdx.x;
    const int tok0 = blockIdx.x << 4;
    for (int idx = tid; idx < 16*NMLP; idx += 256) {
        int e = idx / NMLP, k = idx - e*NMLP;
        sw[e][k] = w2[idx];
    }
    for (int idx = tid; idx < 16*NMLP; idx += 256) {
        int r = idx / NMLP, k = idx - r*NMLP;
        sh[r][k] = g_hid[(size_t)(tok0 + r) * NMLP + k];
    }
    __syncthreads();
    const int e = tid & 15, r = tid >> 4;
    float acc = b2[e];
#pragma unroll
    for (int k = 0; k < NMLP; k += 4) {
        float4 hv = *(const float4*)&sh[r][k];
        float4 wv = *(const float4*)&sw[e][k];
        acc = fmaf(hv.x, wv.x, acc);
        acc = fmaf(hv.y, wv.y, acc);
        acc = fmaf(hv.z, wv.z, acc);
        acc = fmaf(hv.w, wv.w, acc);
    }
    out[(size_t)(tok0 + r) * NX + e] = acc;
}

// ---------------- launch ----------------------------------------------------
extern "C" void kernel_launch(void* const* d_in, const int* in_sizes, int n_in,
                              void* d_out, int out_size) {
    const float* emb  = (const float*)d_in[0];
    const float* U    = (const float*)d_in[1];
    const float* R    = (const float*)d_in[2];
    const float* S    = (const float*)d_in[3];
    const float* tp_w = (const float*)d_in[4];
    const float* tp_b = (const float*)d_in[5];
    const float* q_w  = (const float*)d_in[6];
    const float* q_b  = (const float*)d_in[7];
    const float* k_w  = (const float*)d_in[8];
    const float* k_b  = (const float*)d_in[9];
    const float* v_w  = (const float*)d_in[10];
    const float* v_b  = (const float*)d_in[11];
    const float* wih  = (const float*)d_in[12];
    const float* whh  = (const float*)d_in[13];
    const float* bih  = (const float*)d_in[14];
    const float* bhh  = (const float*)d_in[15];
    const float* w1   = (const float*)d_in[16];
    const float* b1   = (const float*)d_in[17];
    const float* w2   = (const float*)d_in[18];
    const float* b2   = (const float*)d_in[19];
    float* out = (float*)d_out;

    float *processed, *hid, *rus;
    cudaGetSymbolAddress((void**)&processed, g_processed);
    cudaGetSymbolAddress((void**)&hid, g_hid);
    cudaGetSymbolAddress((void**)&rus, g_rus);
    __nv_bfloat16 *wthi, *wtlo, *w1hi, *w1lo;
    cudaGetSymbolAddress((void**)&wthi, g_wthi);
    cudaGetSymbolAddress((void**)&wtlo, g_wtlo);
    cudaGetSymbolAddress((void**)&w1hi, g_w1hi);
    cudaGetSymbolAddress((void**)&w1lo, g_w1lo);

    const int smem128 = 65536 + 4 * 128 * 128;   // 131072
    const int smem64  = 65536 + 4 * 64 * 128;    // 98304
    cudaFuncSetAttribute(k_mma<128>, cudaFuncAttributeMaxDynamicSharedMemorySize,
                         smem128);
    cudaFuncSetAttribute(k_mma<64>, cudaFuncAttributeMaxDynamicSharedMemorySize,
                         smem64);

    k_pre<<<1, 384>>>(q_w, q_b, k_w, k_b, wih, bih, v_w, v_b);
    k_cvt<<<(NP*NE)/1024, 256>>>(tp_w, wthi, wtlo);
    k_cvt<<<(NMLP*NCOMB)/1024, 256>>>(w1, w1hi, w1lo);
    // processed = relu(emb @ tp_w^T + tp_b)
    k_mma<128><<<dim3(NP/128, NTOK/128), 512, smem128>>>(
        emb, NE, NE, emb, NE, wthi, wtlo, NE, tp_b, processed, NP, NE);
    k_scal<<<NTOK/8, 256>>>(R, S);
    k_gru<<<NB*NM, 384>>>(U, whh, bhh);
    // hid = relu([processed | rus] @ w1^T + b1)
    k_mma<64><<<dim3(NMLP/64, NTOK/128), 512, smem64>>>(
        processed, NP, NP, rus, NH, w1hi, w1lo, NCOMB, b1, hid, NMLP, NCOMB);
    k_mlp2<<<NTOK/16, 256>>>(w2, b2, out);
}

// round 15
// speedup vs baseline: 1.2910x; 1.2910x over previous
#include <cuda_runtime.h>
#include <cuda_bf16.h>
#include <math.h>

typedef unsigned long long u64;

#define NB 8
#define NM 4
#define NT 2048
#define NE 768
#define NP 256
#define NH 128
#define NX 16
#define NCOMB 384
#define NMLP 192
#define NKD 64
#define NVD 64
#define NTOK (NB*NM*NT)   /* 65536 */

// ---------------- scratch ----------------------------------------------------
__device__ float g_processed[(size_t)NTOK*NP];
__device__ float g_hid[(size_t)NTOK*NMLP];
__device__ float g_scal[(size_t)NTOK*2];
__device__ float g_rus[(size_t)NTOK*NH];
__device__ float g_wa[NP], g_wb[NP], g_wc[NP];
__device__ float g_cc[3];
__device__ float g_c0[3*NH], g_c1[3*NH], g_c2[3*NH], g_c3[3*NH];
__device__ __nv_bfloat16 g_wthi[NP*NE], g_wtlo[NP*NE];
__device__ __nv_bfloat16 g_w1hi[NMLP*NCOMB], g_w1lo[NMLP*NCOMB];

// ---------------- f32x2 helpers (GRU) ---------------------------------------
__device__ __forceinline__ u64 ffma2(u64 a, u64 b, u64 c) {
    u64 d;
    asm("fma.rn.f32x2 %0, %1, %2, %3;" : "=l"(d) : "l"(a), "l"(b), "l"(c));
    return d;
}
__device__ __forceinline__ float lo2(u64 v) { return __uint_as_float((unsigned)v); }
__device__ __forceinline__ float hi2(u64 v) { return __uint_as_float((unsigned)(v >> 32)); }

// ---------------- mma helpers ------------------------------------------------
__device__ __forceinline__ unsigned smem_u32(const void* p) {
    unsigned a;
    asm("{ .reg .u64 t; cvta.to.shared.u64 t, %1; cvt.u32.u64 %0, t; }"
        : "=r"(a) : "l"(p));
    return a;
}
__device__ __forceinline__ void ldsm4(unsigned& r0, unsigned& r1,
                                      unsigned& r2, unsigned& r3, unsigned addr) {
    asm volatile("ldmatrix.sync.aligned.m8n8.x4.shared.b16 {%0,%1,%2,%3}, [%4];"
                 : "=r"(r0), "=r"(r1), "=r"(r2), "=r"(r3) : "r"(addr));
}
__device__ __forceinline__ void mma16816(float* c, const unsigned* a,
                                         unsigned b0, unsigned b1) {
    asm volatile(
        "mma.sync.aligned.m16n8k16.row.col.f32.bf16.bf16.f32 "
        "{%0,%1,%2,%3}, {%4,%5,%6,%7}, {%8,%9}, {%0,%1,%2,%3};"
        : "+f"(c[0]), "+f"(c[1]), "+f"(c[2]), "+f"(c[3])
        : "r"(a[0]), "r"(a[1]), "r"(a[2]), "r"(a[3]), "r"(b0), "r"(b1));
}
__device__ __forceinline__ void cpasync16(unsigned dst, const void* src) {
    asm volatile("cp.async.ca.shared.global [%0], [%1], 16;"
                 :: "r"(dst), "l"(src) : "memory");
}
#define SW128(x) ((x) ^ (((x) >> 3) & 0x70))

// ---------------- precompute folded weight vectors ---------------------------
__global__ void __launch_bounds__(384) k_pre(
                      const float* __restrict__ qw, const float* __restrict__ qb,
                      const float* __restrict__ kw, const float* __restrict__ kb,
                      const float* __restrict__ wih, const float* __restrict__ bih,
                      const float* __restrict__ vw, const float* __restrict__ vb) {
    int i = threadIdx.x;
    if (i < NP) {
        float a = 0.f, b = 0.f, c = 0.f;
#pragma unroll 4
        for (int k = 0; k < NKD; k++) {
            float q = qw[k*NP + i];
            a = fmaf(q, kw[2*k], a);
            b = fmaf(q, kw[2*k+1], b);
            c = fmaf(q, kb[k], c);
        }
        g_wa[i] = a; g_wb[i] = b; g_wc[i] = c;
    }
    if (i == 0) {
        float a = 0.f, b = 0.f, c = 0.f;
#pragma unroll 4
        for (int k = 0; k < NKD; k++) {
            float q = qb[k];
            a = fmaf(q, kw[2*k], a);
            b = fmaf(q, kw[2*k+1], b);
            c = fmaf(q, kb[k], c);
        }
        g_cc[0] = a; g_cc[1] = b; g_cc[2] = c;
    }
    if (i < 3*NH) {
        const float* wr = wih + (size_t)i*(1 + NVD);
        float c1 = 0.f, c2 = 0.f, c3 = bih[i];
#pragma unroll 4
        for (int v = 0; v < NVD; v++) {
            float w = wr[1 + v];
            c1 = fmaf(w, vw[2*v], c1);
            c2 = fmaf(w, vw[2*v+1], c2);
            c3 = fmaf(w, vb[v], c3);
        }
        g_c0[i] = wr[0]; g_c1[i] = c1; g_c2[i] = c2; g_c3[i] = c3;
    }
}

// ---------------- fp32 -> bf16 hi/lo split (weights only) --------------------
__global__ void __launch_bounds__(256) k_cvt(const float* __restrict__ src,
                                             __nv_bfloat16* __restrict__ hi,
                                             __nv_bfloat16* __restrict__ lo) {
    size_t i4 = ((size_t)blockIdx.x * 256 + threadIdx.x) * 4;
    float4 v = *(const float4*)&src[i4];
    __nv_bfloat16 h0 = __float2bfloat16(v.x);
    __nv_bfloat16 h1 = __float2bfloat16(v.y);
    __nv_bfloat16 h2 = __float2bfloat16(v.z);
    __nv_bfloat16 h3 = __float2bfloat16(v.w);
    __nv_bfloat16 l0 = __float2bfloat16(v.x - __bfloat162float(h0));
    __nv_bfloat16 l1 = __float2bfloat16(v.y - __bfloat162float(h1));
    __nv_bfloat16 l2 = __float2bfloat16(v.z - __bfloat162float(h2));
    __nv_bfloat16 l3 = __float2bfloat16(v.w - __bfloat162float(h3));
    __nv_bfloat162* hp = (__nv_bfloat162*)&hi[i4];
    __nv_bfloat162* lp = (__nv_bfloat162*)&lo[i4];
    hp[0] = __nv_bfloat162(h0, h1); hp[1] = __nv_bfloat162(h2, h3);
    lp[0] = __nv_bfloat162(l0, l1); lp[1] = __nv_bfloat162(l2, l3);
}

// ============================================================================
// Split-bf16 GEMM via mma.sync, f32 A in (hi/lo split fused into the fill).
// Block tile 128 x TN, k-slab 64, 512 threads (16 warps: 4m x 4n).
// 3 products per k16: ah*bh + ah*bl + al*bh.
// flags: bit0 = relu, bit1 = accumulate into existing C. bias may be null.
// ============================================================================
template<int TN>
__global__ void __launch_bounds__(512) k_mma(
    const float* __restrict__ A1, int lda1, int K1,
    const float* __restrict__ A2, int lda2,
    const __nv_bfloat16* __restrict__ Bh, const __nv_bfloat16* __restrict__ Bl,
    int ldb,
    const float* __restrict__ bias, float* __restrict__ C, int ldc, int K,
    int flags)
{
    constexpr int WN  = TN / 4;
    constexpr int NT8 = WN / 8;
    constexpr int BSTG = TN * 128;

    extern __shared__ char smem[];
    char* sA = smem;                 // 2 stages x (16KB hi + 16KB lo)
    char* sB = smem + 65536;         // 2 stages x (BSTG hi + BSTG lo)

    const int tid = threadIdx.x;
    const int w = tid >> 5, lane = tid & 31;
    const int wm = w & 3, wn = w >> 2;
    const int m0 = blockIdx.y << 7, n0 = blockIdx.x * TN;
    const int gid = lane >> 2, tig = lane & 3;

    float acc[2][NT8][4];
#pragma unroll
    for (int mi = 0; mi < 2; ++mi)
#pragma unroll
        for (int nj = 0; nj < NT8; ++nj)
#pragma unroll
            for (int q = 0; q < 4; ++q) acc[mi][nj][q] = 0.f;

    const int a_row = (lane & 7) + ((lane >> 3) & 1) * 8;
    const int a_kh  = (lane >> 4) * 16;
    const int b_row = (lane & 7) + ((lane >> 4) & 1) * 8;
    const int b_kh  = ((lane >> 3) & 1) * 16;

    const unsigned uA = smem_u32(sA), uB = smem_u32(sB);
    const int nslab = K >> 6;
    constexpr int NBF = (TN * 8) / 512;

    auto fillB = [&](int st, int k0) {
#pragma unroll
        for (int ib = 0; ib < NBF; ++ib) {
            int idx = (ib << 9) + tid;
            int r = idx >> 3, k8 = idx & 7;
            unsigned sw = SW128(r * 128 + (k8 << 4));
            size_t go = (size_t)(n0 + r) * ldb + k0 + (k8 << 3);
            cpasync16(uB + st * (2 * BSTG) + sw, &Bh[go]);
            cpasync16(uB + st * (2 * BSTG) + BSTG + sw, &Bl[go]);
        }
        asm volatile("cp.async.commit_group;" ::: "memory");
    };
    auto loadA = [&](int k0, float4* ra) {
        const float* Asrc; int lda, acol;
        if (k0 < K1) { Asrc = A1; lda = lda1; acol = k0; }
        else         { Asrc = A2; lda = lda2; acol = k0 - K1; }
#pragma unroll
        for (int it = 0; it < 4; ++it) {
            int idx = (it << 9) + tid;
            int r = idx >> 4, c4 = idx & 15;
            ra[it] = *(const float4*)&Asrc[(size_t)(m0 + r) * lda + acol + (c4 << 2)];
        }
    };
    auto storeA = [&](int st, const float4* ra) {
#pragma unroll
        for (int it = 0; it < 4; ++it) {
            int idx = (it << 9) + tid;
            int r = idx >> 4, c4 = idx & 15;
            unsigned sw = SW128(r * 128 + (c4 << 3));
            float4 v = ra[it];
            __nv_bfloat16 h0 = __float2bfloat16(v.x);
            __nv_bfloat16 h1 = __float2bfloat16(v.y);
            __nv_bfloat16 h2 = __float2bfloat16(v.z);
            __nv_bfloat16 h3 = __float2bfloat16(v.w);
            __nv_bfloat162 hp0(h0, h1), hp1(h2, h3);
            __nv_bfloat162 lp0(__float2bfloat16(v.x - __bfloat162float(h0)),
                               __float2bfloat16(v.y - __bfloat162float(h1)));
            __nv_bfloat162 lp1(__float2bfloat16(v.z - __bfloat162float(h2)),
                               __float2bfloat16(v.w - __bfloat162float(h3)));
            char* ph = sA + st * 32768 + sw;
            char* pl = sA + st * 32768 + 16384 + sw;
            ((__nv_bfloat162*)ph)[0] = hp0; ((__nv_bfloat162*)ph)[1] = hp1;
            ((__nv_bfloat162*)pl)[0] = lp0; ((__nv_bfloat162*)pl)[1] = lp1;
        }
    };

    {
        float4 ra[4];
        loadA(0, ra);
        storeA(0, ra);
        fillB(0, 0);
        asm volatile("cp.async.wait_group 0;" ::: "memory");
    }
    __syncthreads();

    for (int s = 0; s < nslab; ++s) {
        const int cur = s & 1;
        const bool more = (s + 1 < nslab);
        float4 ra[4];
        if (more) {
            fillB(cur ^ 1, (s + 1) << 6);
            loadA((s + 1) << 6, ra);
        }
        const unsigned uAh = uA + cur * 32768;
        const unsigned uAl = uAh + 16384;
        const unsigned uBh = uB + cur * (2 * BSTG);
        const unsigned uBl = uBh + BSTG;
#pragma unroll
        for (int j = 0; j < 4; ++j) {
            const int kb = j * 32;
            unsigned ah[2][4], al[2][4], bh[NT8][2], bl[NT8][2];
            unsigned aoff = SW128((wm * 32 + a_row) * 128 + kb + a_kh);
            ldsm4(ah[0][0], ah[0][1], ah[0][2], ah[0][3], uAh + aoff);
            ldsm4(ah[1][0], ah[1][1], ah[1][2], ah[1][3], uAh + aoff + 2048);
            ldsm4(al[0][0], al[0][1], al[0][2], al[0][3], uAl + aoff);
            ldsm4(al[1][0], al[1][1], al[1][2], al[1][3], uAl + aoff + 2048);
            unsigned boff = SW128((wn * WN + b_row) * 128 + kb + b_kh);
#pragma unroll
            for (int g = 0; g < NT8 / 2; ++g) {
                ldsm4(bh[2*g][0], bh[2*g][1], bh[2*g+1][0], bh[2*g+1][1],
                      uBh + boff + g * 2048);
                ldsm4(bl[2*g][0], bl[2*g][1], bl[2*g+1][0], bl[2*g+1][1],
                      uBl + boff + g * 2048);
            }
#pragma unroll
            for (int mi = 0; mi < 2; ++mi)
#pragma unroll
                for (int nj = 0; nj < NT8; ++nj)
                    mma16816(acc[mi][nj], ah[mi], bh[nj][0], bh[nj][1]);
#pragma unroll
            for (int mi = 0; mi < 2; ++mi)
#pragma unroll
                for (int nj = 0; nj < NT8; ++nj)
                    mma16816(acc[mi][nj], ah[mi], bl[nj][0], bl[nj][1]);
#pragma unroll
            for (int mi = 0; mi < 2; ++mi)
#pragma unroll
                for (int nj = 0; nj < NT8; ++nj)
                    mma16816(acc[mi][nj], al[mi], bh[nj][0], bh[nj][1]);
        }
        if (more) {
            storeA(cur ^ 1, ra);
            asm volatile("cp.async.wait_group 0;" ::: "memory");
            __syncthreads();
        }
    }

#pragma unroll
    for (int mi = 0; mi < 2; ++mi) {
#pragma unroll
        for (int half = 0; half < 2; ++half) {
            const int row = m0 + wm * 32 + mi * 16 + gid + half * 8;
#pragma unroll
            for (int nj = 0; nj < NT8; ++nj) {
                const int col = n0 + wn * WN + nj * 8 + tig * 2;
                float* cp = &C[(size_t)row * ldc + col];
                float bx = 0.f, by = 0.f;
                if (bias) { float2 bv = *(const float2*)&bias[col]; bx = bv.x; by = bv.y; }
                float v0 = acc[mi][nj][half * 2 + 0] + bx;
                float v1 = acc[mi][nj][half * 2 + 1] + by;
                if (flags & 2) {
                    float2 o = *(const float2*)cp;
                    v0 += o.x; v1 += o.y;
                }
                if (flags & 1) { v0 = fmaxf(v0, 0.f); v1 = fmaxf(v1, 0.f); }
                *(float2*)cp = make_float2(v0, v1);
            }
        }
    }
}

// ---------------- per-token attention scalars (Ar, As) ----------------------
__global__ void __launch_bounds__(256) k_scal(const float* __restrict__ R,
                                              const float* __restrict__ S) {
    int warp = (blockIdx.x * blockDim.x + threadIdx.x) >> 5;
    int lane = threadIdx.x & 31;
    if (warp >= NTOK) return;
    int tok = warp;
    const float* pr = g_processed + (size_t)tok * NP;
    float aa = 0.f, ab = 0.f, ac = 0.f;
#pragma unroll
    for (int p = lane; p < NP; p += 32) {
        float pv = pr[p];
        aa = fmaf(pv, g_wa[p], aa);
        ab = fmaf(pv, g_wb[p], ab);
        ac = fmaf(pv, g_wc[p], ac);
    }
#pragma unroll
    for (int o = 16; o; o >>= 1) {
        aa += __shfl_down_sync(0xffffffffu, aa, o);
        ab += __shfl_down_sync(0xffffffffu, ab, o);
        ac += __shfl_down_sync(0xffffffffu, ac, o);
    }
    if (lane == 0) {
        aa += g_cc[0]; ab += g_cc[1]; ac += g_cc[2];
        int t = tok & (NT - 1);
        int s = tok >> 11;          // b*4+m
        int m = s & 3;
        float sc[3], Ro[3], So[3];
        int n = 0;
        for (int j = 0; j < NM; j++) {
            if (j == m) continue;
            size_t idx = ((size_t)s * NM + j) * NT + t;
            float r = R[idx], sv = S[idx];
            Ro[n] = r; So[n] = sv;
            sc[n] = (fmaf(aa, r, fmaf(ab, sv, ac))) * 0.125f;
            n++;
        }
        float mx = fmaxf(sc[0], fmaxf(sc[1], sc[2]));
        float e0 = expf(sc[0] - mx), e1 = expf(sc[1] - mx), e2 = expf(sc[2] - mx);
        float inv = 1.f / (e0 + e1 + e2);
        g_scal[2*tok]   = (e0*Ro[0] + e1*Ro[1] + e2*Ro[2]) * inv;
        g_scal[2*tok+1] = (e0*So[0] + e1*So[1] + e2*So[2]) * inv;
    }
}

// ---------------- GRU scan: one block per sequence (32 blocks) --------------
__global__ void __launch_bounds__(384, 1) k_gru(const float* __restrict__ U,
                                                const float* __restrict__ whh,
                                                const float* __restrict__ bhh) {
    __shared__ __align__(16) float hbuf[NH];
    __shared__ float exch[3*NH];
    __shared__ float exch_xn[NH];
    __shared__ float su[512], sar[512], sas[512];
    const int s = blockIdx.x;
    const int i = threadIdx.x;

    u64 w2r[NH/2];
    const u64* wp = (const u64*)(whh + (size_t)i * NH);
#pragma unroll
    for (int k = 0; k < NH/2; k++) w2r[k] = wp[k];
    const float bb = bhh[i];
    const float c0 = g_c0[i], c1 = g_c1[i], c2 = g_c2[i], c3 = g_c3[i];

    if (i < NH) hbuf[i] = 0.f;
    const size_t base = (size_t)s * NT;
    float* outp = g_rus + base * NH + i;   // valid only for i < NH

    for (int t0 = 0; t0 < NT; t0 += 512) {
        __syncthreads();
        for (int j = i; j < 512; j += 384) {
            size_t g = base + t0 + j;
            su[j]  = U[g];
            sar[j] = g_scal[2*g];
            sas[j] = g_scal[2*g + 1];
        }
        __syncthreads();
        for (int tt = 0; tt < 512; tt++) {
            float xt = fmaf(su[tt], c0, fmaf(sar[tt], c1, fmaf(sas[tt], c2, c3)));
            u64 a0 = 0ull, a1 = 0ull;
#pragma unroll
            for (int k = 0; k < NH/4; k++) {
                ulonglong2 hv = *(const ulonglong2*)&hbuf[k << 2];
                a0 = ffma2(w2r[2*k],   hv.x, a0);
                a1 = ffma2(w2r[2*k+1], hv.y, a1);
            }
            float acc = bb + ((lo2(a0) + hi2(a0)) + (lo2(a1) + hi2(a1)));
            if (i < 2*NH) exch[i] = acc + xt;
            else { exch[i] = acc; exch_xn[i - 2*NH] = xt; }
            __syncthreads();
            if (i < NH) {
                float r = __fdividef(1.f, 1.f + __expf(-exch[i]));
                float z = __fdividef(1.f, 1.f + __expf(-exch[NH + i]));
                float nn = tanhf(fmaf(r, exch[2*NH + i], exch_xn[i]));
                float hnew = fmaf(z, hbuf[i] - nn, nn);   // (1-z)*n + z*h
                outp[(size_t)(t0 + tt) * NH] = hnew;
                hbuf[i] = hnew;
            }
            __syncthreads();
        }
    }
}

// ---------------- final 192 -> 16 projection --------------------------------
__global__ void __launch_bounds__(256) k_mlp2(const float* __restrict__ w2,
                                              const float* __restrict__ b2,
                                              float* __restrict__ out) {
    __shared__ __align__(16) float sh[16][196];
    __shared__ __align__(16) float sw[16][196];
    const int tid = threadIdx.x;
    const int tok0 = blockIdx.x << 4;
    for (int idx = tid; idx < 16*NMLP; idx += 256) {
        int e = idx / NMLP, k = idx - e*NMLP;
        sw[e][k] = w2[idx];
    }
    for (int idx = tid; idx < 16*NMLP; idx += 256) {
        int r = idx / NMLP, k = idx - r*NMLP;
        sh[r][k] = g_hid[(size_t)(tok0 + r) * NMLP + k];
    }
    __syncthreads();
    const int e = tid & 15, r = tid >> 4;
    float acc = b2[e];
#pragma unroll
    for (int k = 0; k < NMLP; k += 4) {
        float4 hv = *(const float4*)&sh[r][k];
        float4 wv = *(const float4*)&sw[e][k];
        acc = fmaf(hv.x, wv.x, acc);
        acc = fmaf(hv.y, wv.y, acc);
        acc = fmaf(hv.z, wv.z, acc);
        acc = fmaf(hv.w, wv.w, acc);
    }
    out[(size_t)(tok0 + r) * NX + e] = acc;
}

// ---------------- launch ----------------------------------------------------
extern "C" void kernel_launch(void* const* d_in, const int* in_sizes, int n_in,
                              void* d_out, int out_size) {
    const float* emb  = (const float*)d_in[0];
    const float* U    = (const float*)d_in[1];
    const float* R    = (const float*)d_in[2];
    const float* S    = (const float*)d_in[3];
    const float* tp_w = (const float*)d_in[4];
    const float* tp_b = (const float*)d_in[5];
    const float* q_w  = (const float*)d_in[6];
    const float* q_b  = (const float*)d_in[7];
    const float* k_w  = (const float*)d_in[8];
    const float* k_b  = (const float*)d_in[9];
    const float* v_w  = (const float*)d_in[10];
    const float* v_b  = (const float*)d_in[11];
    const float* wih  = (const float*)d_in[12];
    const float* whh  = (const float*)d_in[13];
    const float* bih  = (const float*)d_in[14];
    const float* bhh  = (const float*)d_in[15];
    const float* w1   = (const float*)d_in[16];
    const float* b1   = (const float*)d_in[17];
    const float* w2   = (const float*)d_in[18];
    const float* b2   = (const float*)d_in[19];
    float* out = (float*)d_out;

    float *processed, *hid, *rus;
    cudaGetSymbolAddress((void**)&processed, g_processed);
    cudaGetSymbolAddress((void**)&hid, g_hid);
    cudaGetSymbolAddress((void**)&rus, g_rus);
    __nv_bfloat16 *wthi, *wtlo, *w1hi, *w1lo;
    cudaGetSymbolAddress((void**)&wthi, g_wthi);
    cudaGetSymbolAddress((void**)&wtlo, g_wtlo);
    cudaGetSymbolAddress((void**)&w1hi, g_w1hi);
    cudaGetSymbolAddress((void**)&w1lo, g_w1lo);

    const int smem128 = 65536 + 4 * 128 * 128;   // 131072
    const int smem64  = 65536 + 4 * 64 * 128;    // 98304
    cudaFuncSetAttribute(k_mma<128>, cudaFuncAttributeMaxDynamicSharedMemorySize,
                         smem128);
    cudaFuncSetAttribute(k_mma<64>, cudaFuncAttributeMaxDynamicSharedMemorySize,
                         smem64);

    cudaStream_t s2;
    cudaStreamCreateWithFlags(&s2, cudaStreamNonBlocking);
    cudaEvent_t ev0, ev1;
    cudaEventCreateWithFlags(&ev0, cudaEventDisableTiming);
    cudaEventCreateWithFlags(&ev1, cudaEventDisableTiming);

    k_pre<<<1, 384>>>(q_w, q_b, k_w, k_b, wih, bih, v_w, v_b);
    k_cvt<<<(NP*NE)/1024, 256>>>(tp_w, wthi, wtlo);
    k_cvt<<<(NMLP*NCOMB)/1024, 256>>>(w1, w1hi, w1lo);
    // processed = relu(emb @ tp_w^T + tp_b)
    k_mma<128><<<dim3(NP/128, NTOK/128), 512, smem128>>>(
        emb, NE, NE, emb, NE, wthi, wtlo, NE, tp_b, processed, NP, NE, 1);
    k_scal<<<NTOK/8, 256>>>(R, S);

    // Fork: mlp1a (hid = processed @ w1[:, :256]^T + b1, no relu) under the GRU.
    // GEMM blocks (123r x 512t) cannot co-reside with GRU blocks (166r x 384t),
    // so they fill only the 116 GRU-idle SMs.
    cudaEventRecord(ev0, 0);
    cudaStreamWaitEvent(s2, ev0, 0);
    k_mma<64><<<dim3(NMLP/64, NTOK/128), 512, smem64, s2>>>(
        processed, NP, NP, processed, NP, w1hi, w1lo, NCOMB, b1,
        hid, NMLP, NP, 0);
    cudaEventRecord(ev1, s2);

    k_gru<<<NB*NM, 384>>>(U, whh, bhh);

    // Join, then hid = relu(hid + rus @ w1[:, 256:384]^T)
    cudaStreamWaitEvent(0, ev1, 0);
    k_mma<64><<<dim3(NMLP/64, NTOK/128), 512, smem64>>>(
        rus, NH, NH, rus, NH, w1hi + NP, w1lo + NP, NCOMB, nullptr,
        hid, NMLP, NH, 3);
    k_mlp2<<<NTOK/16, 256>>>(w2, b2, out);

    cudaEventDestroy(ev0);
    cudaEventDestroy(ev1);
    cudaStreamDestroy(s2);
}

// round 16
// speedup vs baseline: 1.3518x; 1.0471x over previous
#include <cuda_runtime.h>
#include <cuda_bf16.h>
#include <math.h>

typedef unsigned long long u64;

#define NB 8
#define NM 4
#define NT 2048
#define NE 768
#define NP 256
#define NH 128
#define NX 16
#define NCOMB 384
#define NMLP 192
#define NKD 64
#define NVD 64
#define NTOK (NB*NM*NT)   /* 65536 */

// ---------------- scratch ----------------------------------------------------
__device__ float g_processed[(size_t)NTOK*NP];
__device__ float g_hid[(size_t)NTOK*NMLP];
__device__ float g_scal[(size_t)NTOK*2];
__device__ float g_rus[(size_t)NTOK*NH];
__device__ float g_wa[NP], g_wb[NP], g_wc[NP];
__device__ float g_cc[3];
__device__ float g_c0[3*NH], g_c1[3*NH], g_c2[3*NH], g_c3[3*NH];
__device__ __nv_bfloat16 g_wthi[NP*NE], g_wtlo[NP*NE];
__device__ __nv_bfloat16 g_w1hi[NMLP*NCOMB], g_w1lo[NMLP*NCOMB];

// ---------------- f32x2 helpers (GRU) ---------------------------------------
__device__ __forceinline__ u64 ffma2(u64 a, u64 b, u64 c) {
    u64 d;
    asm("fma.rn.f32x2 %0, %1, %2, %3;" : "=l"(d) : "l"(a), "l"(b), "l"(c));
    return d;
}
__device__ __forceinline__ float lo2(u64 v) { return __uint_as_float((unsigned)v); }
__device__ __forceinline__ float hi2(u64 v) { return __uint_as_float((unsigned)(v >> 32)); }

// ---------------- mma helpers ------------------------------------------------
__device__ __forceinline__ unsigned smem_u32(const void* p) {
    unsigned a;
    asm("{ .reg .u64 t; cvta.to.shared.u64 t, %1; cvt.u32.u64 %0, t; }"
        : "=r"(a) : "l"(p));
    return a;
}
__device__ __forceinline__ void ldsm4(unsigned& r0, unsigned& r1,
                                      unsigned& r2, unsigned& r3, unsigned addr) {
    asm volatile("ldmatrix.sync.aligned.m8n8.x4.shared.b16 {%0,%1,%2,%3}, [%4];"
                 : "=r"(r0), "=r"(r1), "=r"(r2), "=r"(r3) : "r"(addr));
}
__device__ __forceinline__ void mma16816(float* c, const unsigned* a,
                                         unsigned b0, unsigned b1) {
    asm volatile(
        "mma.sync.aligned.m16n8k16.row.col.f32.bf16.bf16.f32 "
        "{%0,%1,%2,%3}, {%4,%5,%6,%7}, {%8,%9}, {%0,%1,%2,%3};"
        : "+f"(c[0]), "+f"(c[1]), "+f"(c[2]), "+f"(c[3])
        : "r"(a[0]), "r"(a[1]), "r"(a[2]), "r"(a[3]), "r"(b0), "r"(b1));
}
__device__ __forceinline__ void cpasync16(unsigned dst, const void* src) {
    asm volatile("cp.async.ca.shared.global [%0], [%1], 16;"
                 :: "r"(dst), "l"(src) : "memory");
}
#define SW128(x) ((x) ^ (((x) >> 3) & 0x70))

// ---------------- precompute folded weight vectors ---------------------------
__global__ void __launch_bounds__(384) k_pre(
                      const float* __restrict__ qw, const float* __restrict__ qb,
                      const float* __restrict__ kw, const float* __restrict__ kb,
                      const float* __restrict__ wih, const float* __restrict__ bih,
                      const float* __restrict__ vw, const float* __restrict__ vb) {
    int i = threadIdx.x;
    if (i < NP) {
        float a = 0.f, b = 0.f, c = 0.f;
#pragma unroll 4
        for (int k = 0; k < NKD; k++) {
            float q = qw[k*NP + i];
            a = fmaf(q, kw[2*k], a);
            b = fmaf(q, kw[2*k+1], b);
            c = fmaf(q, kb[k], c);
        }
        g_wa[i] = a; g_wb[i] = b; g_wc[i] = c;
    }
    if (i == 0) {
        float a = 0.f, b = 0.f, c = 0.f;
#pragma unroll 4
        for (int k = 0; k < NKD; k++) {
            float q = qb[k];
            a = fmaf(q, kw[2*k], a);
            b = fmaf(q, kw[2*k+1], b);
            c = fmaf(q, kb[k], c);
        }
        g_cc[0] = a; g_cc[1] = b; g_cc[2] = c;
    }
    if (i < 3*NH) {
        const float* wr = wih + (size_t)i*(1 + NVD);
        float c1 = 0.f, c2 = 0.f, c3 = bih[i];
#pragma unroll 4
        for (int v = 0; v < NVD; v++) {
            float w = wr[1 + v];
            c1 = fmaf(w, vw[2*v], c1);
            c2 = fmaf(w, vw[2*v+1], c2);
            c3 = fmaf(w, vb[v], c3);
        }
        g_c0[i] = wr[0]; g_c1[i] = c1; g_c2[i] = c2; g_c3[i] = c3;
    }
}

// ---------------- fp32 -> bf16 hi/lo split (weights only) --------------------
__global__ void __launch_bounds__(256) k_cvt(const float* __restrict__ src,
                                             __nv_bfloat16* __restrict__ hi,
                                             __nv_bfloat16* __restrict__ lo) {
    size_t i4 = ((size_t)blockIdx.x * 256 + threadIdx.x) * 4;
    float4 v = *(const float4*)&src[i4];
    __nv_bfloat16 h0 = __float2bfloat16(v.x);
    __nv_bfloat16 h1 = __float2bfloat16(v.y);
    __nv_bfloat16 h2 = __float2bfloat16(v.z);
    __nv_bfloat16 h3 = __float2bfloat16(v.w);
    __nv_bfloat16 l0 = __float2bfloat16(v.x - __bfloat162float(h0));
    __nv_bfloat16 l1 = __float2bfloat16(v.y - __bfloat162float(h1));
    __nv_bfloat16 l2 = __float2bfloat16(v.z - __bfloat162float(h2));
    __nv_bfloat16 l3 = __float2bfloat16(v.w - __bfloat162float(h3));
    __nv_bfloat162* hp = (__nv_bfloat162*)&hi[i4];
    __nv_bfloat162* lp = (__nv_bfloat162*)&lo[i4];
    hp[0] = __nv_bfloat162(h0, h1); hp[1] = __nv_bfloat162(h2, h3);
    lp[0] = __nv_bfloat162(l0, l1); lp[1] = __nv_bfloat162(l2, l3);
}

// ============================================================================
// Split-bf16 GEMM via mma.sync, f32 A in (hi/lo split fused into the fill).
// Block tile 128 x TN, k-slab 64, 512 threads (16 warps: 4m x 4n).
// 3 products per k16: ah*bh + ah*bl + al*bh.
// flags: bit0 = relu, bit1 = accumulate into existing C. bias may be null.
// ============================================================================
template<int TN>
__global__ void __launch_bounds__(512) k_mma(
    const float* __restrict__ A1, int lda1, int K1,
    const float* __restrict__ A2, int lda2,
    const __nv_bfloat16* __restrict__ Bh, const __nv_bfloat16* __restrict__ Bl,
    int ldb,
    const float* __restrict__ bias, float* __restrict__ C, int ldc, int K,
    int flags)
{
    constexpr int WN  = TN / 4;
    constexpr int NT8 = WN / 8;
    constexpr int BSTG = TN * 128;

    extern __shared__ char smem[];
    char* sA = smem;                 // 2 stages x (16KB hi + 16KB lo)
    char* sB = smem + 65536;         // 2 stages x (BSTG hi + BSTG lo)

    const int tid = threadIdx.x;
    const int w = tid >> 5, lane = tid & 31;
    const int wm = w & 3, wn = w >> 2;
    const int m0 = blockIdx.y << 7, n0 = blockIdx.x * TN;
    const int gid = lane >> 2, tig = lane & 3;

    float acc[2][NT8][4];
#pragma unroll
    for (int mi = 0; mi < 2; ++mi)
#pragma unroll
        for (int nj = 0; nj < NT8; ++nj)
#pragma unroll
            for (int q = 0; q < 4; ++q) acc[mi][nj][q] = 0.f;

    const int a_row = (lane & 7) + ((lane >> 3) & 1) * 8;
    const int a_kh  = (lane >> 4) * 16;
    const int b_row = (lane & 7) + ((lane >> 4) & 1) * 8;
    const int b_kh  = ((lane >> 3) & 1) * 16;

    const unsigned uA = smem_u32(sA), uB = smem_u32(sB);
    const int nslab = K >> 6;
    constexpr int NBF = (TN * 8) / 512;

    auto fillB = [&](int st, int k0) {
#pragma unroll
        for (int ib = 0; ib < NBF; ++ib) {
            int idx = (ib << 9) + tid;
            int r = idx >> 3, k8 = idx & 7;
            unsigned sw = SW128(r * 128 + (k8 << 4));
            size_t go = (size_t)(n0 + r) * ldb + k0 + (k8 << 3);
            cpasync16(uB + st * (2 * BSTG) + sw, &Bh[go]);
            cpasync16(uB + st * (2 * BSTG) + BSTG + sw, &Bl[go]);
        }
        asm volatile("cp.async.commit_group;" ::: "memory");
    };
    auto loadA = [&](int k0, float4* ra) {
        const float* Asrc; int lda, acol;
        if (k0 < K1) { Asrc = A1; lda = lda1; acol = k0; }
        else         { Asrc = A2; lda = lda2; acol = k0 - K1; }
#pragma unroll
        for (int it = 0; it < 4; ++it) {
            int idx = (it << 9) + tid;
            int r = idx >> 4, c4 = idx & 15;
            ra[it] = *(const float4*)&Asrc[(size_t)(m0 + r) * lda + acol + (c4 << 2)];
        }
    };
    auto storeA = [&](int st, const float4* ra) {
#pragma unroll
        for (int it = 0; it < 4; ++it) {
            int idx = (it << 9) + tid;
            int r = idx >> 4, c4 = idx & 15;
            unsigned sw = SW128(r * 128 + (c4 << 3));
            float4 v = ra[it];
            __nv_bfloat16 h0 = __float2bfloat16(v.x);
            __nv_bfloat16 h1 = __float2bfloat16(v.y);
            __nv_bfloat16 h2 = __float2bfloat16(v.z);
            __nv_bfloat16 h3 = __float2bfloat16(v.w);
            __nv_bfloat162 hp0(h0, h1), hp1(h2, h3);
            __nv_bfloat162 lp0(__float2bfloat16(v.x - __bfloat162float(h0)),
                               __float2bfloat16(v.y - __bfloat162float(h1)));
            __nv_bfloat162 lp1(__float2bfloat16(v.z - __bfloat162float(h2)),
                               __float2bfloat16(v.w - __bfloat162float(h3)));
            char* ph = sA + st * 32768 + sw;
            char* pl = sA + st * 32768 + 16384 + sw;
            ((__nv_bfloat162*)ph)[0] = hp0; ((__nv_bfloat162*)ph)[1] = hp1;
            ((__nv_bfloat162*)pl)[0] = lp0; ((__nv_bfloat162*)pl)[1] = lp1;
        }
    };

    {
        float4 ra[4];
        loadA(0, ra);
        storeA(0, ra);
        fillB(0, 0);
        asm volatile("cp.async.wait_group 0;" ::: "memory");
    }
    __syncthreads();

    for (int s = 0; s < nslab; ++s) {
        const int cur = s & 1;
        const bool more = (s + 1 < nslab);
        float4 ra[4];
        if (more) {
            fillB(cur ^ 1, (s + 1) << 6);
            loadA((s + 1) << 6, ra);
        }
        const unsigned uAh = uA + cur * 32768;
        const unsigned uAl = uAh + 16384;
        const unsigned uBh = uB + cur * (2 * BSTG);
        const unsigned uBl = uBh + BSTG;
#pragma unroll
        for (int j = 0; j < 4; ++j) {
            const int kb = j * 32;
            unsigned ah[2][4], al[2][4], bh[NT8][2], bl[NT8][2];
            unsigned aoff = SW128((wm * 32 + a_row) * 128 + kb + a_kh);
            ldsm4(ah[0][0], ah[0][1], ah[0][2], ah[0][3], uAh + aoff);
            ldsm4(ah[1][0], ah[1][1], ah[1][2], ah[1][3], uAh + aoff + 2048);
            ldsm4(al[0][0], al[0][1], al[0][2], al[0][3], uAl + aoff);
            ldsm4(al[1][0], al[1][1], al[1][2], al[1][3], uAl + aoff + 2048);
            unsigned boff = SW128((wn * WN + b_row) * 128 + kb + b_kh);
#pragma unroll
            for (int g = 0; g < NT8 / 2; ++g) {
                ldsm4(bh[2*g][0], bh[2*g][1], bh[2*g+1][0], bh[2*g+1][1],
                      uBh + boff + g * 2048);
                ldsm4(bl[2*g][0], bl[2*g][1], bl[2*g+1][0], bl[2*g+1][1],
                      uBl + boff + g * 2048);
            }
#pragma unroll
            for (int mi = 0; mi < 2; ++mi)
#pragma unroll
                for (int nj = 0; nj < NT8; ++nj)
                    mma16816(acc[mi][nj], ah[mi], bh[nj][0], bh[nj][1]);
#pragma unroll
            for (int mi = 0; mi < 2; ++mi)
#pragma unroll
                for (int nj = 0; nj < NT8; ++nj)
                    mma16816(acc[mi][nj], ah[mi], bl[nj][0], bl[nj][1]);
#pragma unroll
            for (int mi = 0; mi < 2; ++mi)
#pragma unroll
                for (int nj = 0; nj < NT8; ++nj)
                    mma16816(acc[mi][nj], al[mi], bh[nj][0], bh[nj][1]);
        }
        if (more) {
            storeA(cur ^ 1, ra);
            asm volatile("cp.async.wait_group 0;" ::: "memory");
            __syncthreads();
        }
    }

#pragma unroll
    for (int mi = 0; mi < 2; ++mi) {
#pragma unroll
        for (int half = 0; half < 2; ++half) {
            const int row = m0 + wm * 32 + mi * 16 + gid + half * 8;
#pragma unroll
            for (int nj = 0; nj < NT8; ++nj) {
                const int col = n0 + wn * WN + nj * 8 + tig * 2;
                float* cp = &C[(size_t)row * ldc + col];
                float bx = 0.f, by = 0.f;
                if (bias) { float2 bv = *(const float2*)&bias[col]; bx = bv.x; by = bv.y; }
                float v0 = acc[mi][nj][half * 2 + 0] + bx;
                float v1 = acc[mi][nj][half * 2 + 1] + by;
                if (flags & 2) {
                    float2 o = *(const float2*)cp;
                    v0 += o.x; v1 += o.y;
                }
                if (flags & 1) { v0 = fmaxf(v0, 0.f); v1 = fmaxf(v1, 0.f); }
                *(float2*)cp = make_float2(v0, v1);
            }
        }
    }
}

// ---------------- per-token attention scalars (Ar, As) ----------------------
__global__ void __launch_bounds__(256) k_scal(const float* __restrict__ R,
                                              const float* __restrict__ S) {
    int warp = (blockIdx.x * blockDim.x + threadIdx.x) >> 5;
    int lane = threadIdx.x & 31;
    if (warp >= NTOK) return;
    int tok = warp;
    const float* pr = g_processed + (size_t)tok * NP;
    float aa = 0.f, ab = 0.f, ac = 0.f;
#pragma unroll
    for (int p = lane; p < NP; p += 32) {
        float pv = pr[p];
        aa = fmaf(pv, g_wa[p], aa);
        ab = fmaf(pv, g_wb[p], ab);
        ac = fmaf(pv, g_wc[p], ac);
    }
#pragma unroll
    for (int o = 16; o; o >>= 1) {
        aa += __shfl_down_sync(0xffffffffu, aa, o);
        ab += __shfl_down_sync(0xffffffffu, ab, o);
        ac += __shfl_down_sync(0xffffffffu, ac, o);
    }
    if (lane == 0) {
        aa += g_cc[0]; ab += g_cc[1]; ac += g_cc[2];
        int t = tok & (NT - 1);
        int s = tok >> 11;          // b*4+m
        int m = s & 3;
        float sc[3], Ro[3], So[3];
        int n = 0;
        for (int j = 0; j < NM; j++) {
            if (j == m) continue;
            size_t idx = ((size_t)s * NM + j) * NT + t;
            float r = R[idx], sv = S[idx];
            Ro[n] = r; So[n] = sv;
            sc[n] = (fmaf(aa, r, fmaf(ab, sv, ac))) * 0.125f;
            n++;
        }
        float mx = fmaxf(sc[0], fmaxf(sc[1], sc[2]));
        float e0 = expf(sc[0] - mx), e1 = expf(sc[1] - mx), e2 = expf(sc[2] - mx);
        float inv = 1.f / (e0 + e1 + e2);
        g_scal[2*tok]   = (e0*Ro[0] + e1*Ro[1] + e2*Ro[2]) * inv;
        g_scal[2*tok+1] = (e0*So[0] + e1*So[1] + e2*So[2]) * inv;
    }
}

// ---------------- GRU scan: one block per sequence (32 blocks) --------------
__global__ void __launch_bounds__(384, 1) k_gru(const float* __restrict__ U,
                                                const float* __restrict__ whh,
                                                const float* __restrict__ bhh) {
    __shared__ __align__(16) float hbuf[NH];
    __shared__ float exch[3*NH];
    __shared__ float exch_xn[NH];
    __shared__ float su[512], sar[512], sas[512];
    const int s = blockIdx.x;
    const int i = threadIdx.x;

    u64 w2r[NH/2];
    const u64* wp = (const u64*)(whh + (size_t)i * NH);
#pragma unroll
    for (int k = 0; k < NH/2; k++) w2r[k] = wp[k];
    const float bb = bhh[i];
    const float c0 = g_c0[i], c1 = g_c1[i], c2 = g_c2[i], c3 = g_c3[i];

    if (i < NH) hbuf[i] = 0.f;
    const size_t base = (size_t)s * NT;
    float* outp = g_rus + base * NH + i;   // valid only for i < NH

    for (int t0 = 0; t0 < NT; t0 += 512) {
        __syncthreads();
        for (int j = i; j < 512; j += 384) {
            size_t g = base + t0 + j;
            su[j]  = U[g];
            sar[j] = g_scal[2*g];
            sas[j] = g_scal[2*g + 1];
        }
        __syncthreads();
        for (int tt = 0; tt < 512; tt++) {
            float xt = fmaf(su[tt], c0, fmaf(sar[tt], c1, fmaf(sas[tt], c2, c3)));
            u64 a0 = 0ull, a1 = 0ull;
#pragma unroll
            for (int k = 0; k < NH/4; k++) {
                ulonglong2 hv = *(const ulonglong2*)&hbuf[k << 2];
                a0 = ffma2(w2r[2*k],   hv.x, a0);
                a1 = ffma2(w2r[2*k+1], hv.y, a1);
            }
            float acc = bb + ((lo2(a0) + hi2(a0)) + (lo2(a1) + hi2(a1)));
            if (i < 2*NH) exch[i] = acc + xt;
            else { exch[i] = acc; exch_xn[i - 2*NH] = xt; }
            __syncthreads();
            if (i < NH) {
                float r = __fdividef(1.f, 1.f + __expf(-exch[i]));
                float z = __fdividef(1.f, 1.f + __expf(-exch[NH + i]));
                float nn = tanhf(fmaf(r, exch[2*NH + i], exch_xn[i]));
                float hnew = fmaf(z, hbuf[i] - nn, nn);   // (1-z)*n + z*h
                outp[(size_t)(t0 + tt) * NH] = hnew;
                hbuf[i] = hnew;
            }
            __syncthreads();
        }
    }
}

// ---------------- final 192 -> 16 projection --------------------------------
__global__ void __launch_bounds__(256) k_mlp2(const float* __restrict__ w2,
                                              const float* __restrict__ b2,
                                              float* __restrict__ out) {
    __shared__ __align__(16) float sh[16][196];
    __shared__ __align__(16) float sw[16][196];
    const int tid = threadIdx.x;
    const int tok0 = blockIdx.x << 4;
    for (int idx = tid; idx < 16*NMLP; idx += 256) {
        int e = idx / NMLP, k = idx - e*NMLP;
        sw[e][k] = w2[idx];
    }
    for (int idx = tid; idx < 16*NMLP; idx += 256) {
        int r = idx / NMLP, k = idx - r*NMLP;
        sh[r][k] = g_hid[(size_t)(tok0 + r) * NMLP + k];
    }
    __syncthreads();
    const int e = tid & 15, r = tid >> 4;
    float acc = b2[e];
#pragma unroll
    for (int k = 0; k < NMLP; k += 4) {
        float4 hv = *(const float4*)&sh[r][k];
        float4 wv = *(const float4*)&sw[e][k];
        acc = fmaf(hv.x, wv.x, acc);
        acc = fmaf(hv.y, wv.y, acc);
        acc = fmaf(hv.z, wv.z, acc);
        acc = fmaf(hv.w, wv.w, acc);
    }
    out[(size_t)(tok0 + r) * NX + e] = acc;
}

// ---------------- launch ----------------------------------------------------
extern "C" void kernel_launch(void* const* d_in, const int* in_sizes, int n_in,
                              void* d_out, int out_size) {
    const float* emb  = (const float*)d_in[0];
    const float* U    = (const float*)d_in[1];
    const float* R    = (const float*)d_in[2];
    const float* S    = (const float*)d_in[3];
    const float* tp_w = (const float*)d_in[4];
    const float* tp_b = (const float*)d_in[5];
    const float* q_w  = (const float*)d_in[6];
    const float* q_b  = (const float*)d_in[7];
    const float* k_w  = (const float*)d_in[8];
    const float* k_b  = (const float*)d_in[9];
    const float* v_w  = (const float*)d_in[10];
    const float* v_b  = (const float*)d_in[11];
    const float* wih  = (const float*)d_in[12];
    const float* whh  = (const float*)d_in[13];
    const float* bih  = (const float*)d_in[14];
    const float* bhh  = (const float*)d_in[15];
    const float* w1   = (const float*)d_in[16];
    const float* b1   = (const float*)d_in[17];
    const float* w2   = (const float*)d_in[18];
    const float* b2   = (const float*)d_in[19];
    float* out = (float*)d_out;

    float *processed, *hid, *rus;
    cudaGetSymbolAddress((void**)&processed, g_processed);
    cudaGetSymbolAddress((void**)&hid, g_hid);
    cudaGetSymbolAddress((void**)&rus, g_rus);
    __nv_bfloat16 *wthi, *wtlo, *w1hi, *w1lo;
    cudaGetSymbolAddress((void**)&wthi, g_wthi);
    cudaGetSymbolAddress((void**)&wtlo, g_wtlo);
    cudaGetSymbolAddress((void**)&w1hi, g_w1hi);
    cudaGetSymbolAddress((void**)&w1lo, g_w1lo);

    const int smem128 = 65536 + 4 * 128 * 128;   // 131072
    const int smem64  = 65536 + 4 * 64 * 128;    // 98304
    cudaFuncSetAttribute(k_mma<128>, cudaFuncAttributeMaxDynamicSharedMemorySize,
                         smem128);
    cudaFuncSetAttribute(k_mma<64>, cudaFuncAttributeMaxDynamicSharedMemorySize,
                         smem64);

    // low-priority stream for the overlapped GEMM (GRU must win SM dispatch)
    int prLo = 0, prHi = 0;
    cudaDeviceGetStreamPriorityRange(&prLo, &prHi);   // prLo = numerically lowest prio
    cudaStream_t s2;
    cudaStreamCreateWithPriority(&s2, cudaStreamNonBlocking, prLo);
    cudaEvent_t ev0, ev1;
    cudaEventCreateWithFlags(&ev0, cudaEventDisableTiming);
    cudaEventCreateWithFlags(&ev1, cudaEventDisableTiming);

    k_pre<<<1, 384>>>(q_w, q_b, k_w, k_b, wih, bih, v_w, v_b);
    k_cvt<<<(NP*NE)/1024, 256>>>(tp_w, wthi, wtlo);
    k_cvt<<<(NMLP*NCOMB)/1024, 256>>>(w1, w1hi, w1lo);
    // processed = relu(emb @ tp_w^T + tp_b)
    k_mma<128><<<dim3(NP/128, NTOK/128), 512, smem128>>>(
        emb, NE, NE, emb, NE, wthi, wtlo, NE, tp_b, processed, NP, NE, 1);
    k_scal<<<NTOK/8, 256>>>(R, S);
    cudaEventRecord(ev0, 0);

    // GRU FIRST (captured before mlp1a -> its 32 blocks get SMs immediately)
    k_gru<<<NB*NM, 384>>>(U, whh, bhh);

    // mlp1a (hid = processed @ w1[:, :256]^T + b1, no relu) on low-prio stream,
    // filling only the 116 SMs the GRU leaves free (blocks cannot co-reside).
    cudaStreamWaitEvent(s2, ev0, 0);
    k_mma<64><<<dim3(NMLP/64, NTOK/128), 512, smem64, s2>>>(
        processed, NP, NP, processed, NP, w1hi, w1lo, NCOMB, b1,
        hid, NMLP, NP, 0);
    cudaEventRecord(ev1, s2);

    // Join, then hid = relu(hid + rus @ w1[:, 256:384]^T)
    cudaStreamWaitEvent(0, ev1, 0);
    k_mma<64><<<dim3(NMLP/64, NTOK/128), 512, smem64>>>(
        rus, NH, NH, rus, NH, w1hi + NP, w1lo + NP, NCOMB, nullptr,
        hid, NMLP, NH, 3);
    k_mlp2<<<NTOK/16, 256>>>(w2, b2, out);

    cudaEventDestroy(ev0);
    cudaEventDestroy(ev1);
    cudaStreamDestroy(s2);
}

// round 17
// speedup vs baseline: 1.3564x; 1.0034x over previous
#include <cuda_runtime.h>
#include <cuda_bf16.h>
#include <math.h>

typedef unsigned long long u64;

#define NB 8
#define NM 4
#define NT 2048
#define NE 768
#define NP 256
#define NH 128
#define NX 16
#define NCOMB 384
#define NMLP 192
#define NKD 64
#define NVD 64
#define NTOK (NB*NM*NT)   /* 65536 */

// ---------------- scratch ----------------------------------------------------
__device__ float g_processed[(size_t)NTOK*NP];
__device__ float g_hid[(size_t)NTOK*NMLP];
__device__ float g_scal[(size_t)NTOK*2];
__device__ float g_rus[(size_t)NTOK*NH];
__device__ float g_wa[NP], g_wb[NP], g_wc[NP];
__device__ float g_cc[3];
__device__ float g_c0[3*NH], g_c1[3*NH], g_c2[3*NH], g_c3[3*NH];
__device__ __nv_bfloat16 g_wthi[NP*NE], g_wtlo[NP*NE];
__device__ __nv_bfloat16 g_w1hi[NMLP*NCOMB], g_w1lo[NMLP*NCOMB];

// ---------------- f32x2 helpers (GRU) ---------------------------------------
__device__ __forceinline__ u64 ffma2(u64 a, u64 b, u64 c) {
    u64 d;
    asm("fma.rn.f32x2 %0, %1, %2, %3;" : "=l"(d) : "l"(a), "l"(b), "l"(c));
    return d;
}
__device__ __forceinline__ float lo2(u64 v) { return __uint_as_float((unsigned)v); }
__device__ __forceinline__ float hi2(u64 v) { return __uint_as_float((unsigned)(v >> 32)); }

// ---------------- mma helpers ------------------------------------------------
__device__ __forceinline__ unsigned smem_u32(const void* p) {
    unsigned a;
    asm("{ .reg .u64 t; cvta.to.shared.u64 t, %1; cvt.u32.u64 %0, t; }"
        : "=r"(a) : "l"(p));
    return a;
}
__device__ __forceinline__ void ldsm4(unsigned& r0, unsigned& r1,
                                      unsigned& r2, unsigned& r3, unsigned addr) {
    asm volatile("ldmatrix.sync.aligned.m8n8.x4.shared.b16 {%0,%1,%2,%3}, [%4];"
                 : "=r"(r0), "=r"(r1), "=r"(r2), "=r"(r3) : "r"(addr));
}
__device__ __forceinline__ void mma16816(float* c, const unsigned* a,
                                         unsigned b0, unsigned b1) {
    asm volatile(
        "mma.sync.aligned.m16n8k16.row.col.f32.bf16.bf16.f32 "
        "{%0,%1,%2,%3}, {%4,%5,%6,%7}, {%8,%9}, {%0,%1,%2,%3};"
        : "+f"(c[0]), "+f"(c[1]), "+f"(c[2]), "+f"(c[3])
        : "r"(a[0]), "r"(a[1]), "r"(a[2]), "r"(a[3]), "r"(b0), "r"(b1));
}
__device__ __forceinline__ void cpasync16(unsigned dst, const void* src) {
    asm volatile("cp.async.ca.shared.global [%0], [%1], 16;"
                 :: "r"(dst), "l"(src) : "memory");
}
#define SW128(x) ((x) ^ (((x) >> 3) & 0x70))

// ---------------- precompute folded weight vectors ---------------------------
__global__ void __launch_bounds__(384) k_pre(
                      const float* __restrict__ qw, const float* __restrict__ qb,
                      const float* __restrict__ kw, const float* __restrict__ kb,
                      const float* __restrict__ wih, const float* __restrict__ bih,
                      const float* __restrict__ vw, const float* __restrict__ vb) {
    int i = threadIdx.x;
    if (i < NP) {
        float a = 0.f, b = 0.f, c = 0.f;
#pragma unroll 4
        for (int k = 0; k < NKD; k++) {
            float q = qw[k*NP + i];
            a = fmaf(q, kw[2*k], a);
            b = fmaf(q, kw[2*k+1], b);
            c = fmaf(q, kb[k], c);
        }
        g_wa[i] = a; g_wb[i] = b; g_wc[i] = c;
    }
    if (i == 0) {
        float a = 0.f, b = 0.f, c = 0.f;
#pragma unroll 4
        for (int k = 0; k < NKD; k++) {
            float q = qb[k];
            a = fmaf(q, kw[2*k], a);
            b = fmaf(q, kw[2*k+1], b);
            c = fmaf(q, kb[k], c);
        }
        g_cc[0] = a; g_cc[1] = b; g_cc[2] = c;
    }
    if (i < 3*NH) {
        const float* wr = wih + (size_t)i*(1 + NVD);
        float c1 = 0.f, c2 = 0.f, c3 = bih[i];
#pragma unroll 4
        for (int v = 0; v < NVD; v++) {
            float w = wr[1 + v];
            c1 = fmaf(w, vw[2*v], c1);
            c2 = fmaf(w, vw[2*v+1], c2);
            c3 = fmaf(w, vb[v], c3);
        }
        g_c0[i] = wr[0]; g_c1[i] = c1; g_c2[i] = c2; g_c3[i] = c3;
    }
}

// ---------------- fp32 -> bf16 hi/lo split (weights only) --------------------
__global__ void __launch_bounds__(256) k_cvt(const float* __restrict__ src,
                                             __nv_bfloat16* __restrict__ hi,
                                             __nv_bfloat16* __restrict__ lo) {
    size_t i4 = ((size_t)blockIdx.x * 256 + threadIdx.x) * 4;
    float4 v = *(const float4*)&src[i4];
    __nv_bfloat16 h0 = __float2bfloat16(v.x);
    __nv_bfloat16 h1 = __float2bfloat16(v.y);
    __nv_bfloat16 h2 = __float2bfloat16(v.z);
    __nv_bfloat16 h3 = __float2bfloat16(v.w);
    __nv_bfloat16 l0 = __float2bfloat16(v.x - __bfloat162float(h0));
    __nv_bfloat16 l1 = __float2bfloat16(v.y - __bfloat162float(h1));
    __nv_bfloat16 l2 = __float2bfloat16(v.z - __bfloat162float(h2));
    __nv_bfloat16 l3 = __float2bfloat16(v.w - __bfloat162float(h3));
    __nv_bfloat162* hp = (__nv_bfloat162*)&hi[i4];
    __nv_bfloat162* lp = (__nv_bfloat162*)&lo[i4];
    hp[0] = __nv_bfloat162(h0, h1); hp[1] = __nv_bfloat162(h2, h3);
    lp[0] = __nv_bfloat162(l0, l1); lp[1] = __nv_bfloat162(l2, l3);
}

// ============================================================================
// Split-bf16 GEMM via mma.sync, f32 A in (hi/lo split fused into the fill).
// Block tile 128 x TN, k-slab 64, 512 threads (16 warps: 4m x 4n).
// 3 products per k16: ah*bh + ah*bl + al*bh.
// flags: bit0 = relu, bit1 = accumulate into existing C. bias may be null.
// ============================================================================
template<int TN>
__global__ void __launch_bounds__(512) k_mma(
    const float* __restrict__ A1, int lda1, int K1,
    const float* __restrict__ A2, int lda2,
    const __nv_bfloat16* __restrict__ Bh, const __nv_bfloat16* __restrict__ Bl,
    int ldb,
    const float* __restrict__ bias, float* __restrict__ C, int ldc, int K,
    int flags)
{
    constexpr int WN  = TN / 4;
    constexpr int NT8 = WN / 8;
    constexpr int BSTG = TN * 128;

    extern __shared__ char smem[];
    char* sA = smem;
    char* sB = smem + 65536;

    const int tid = threadIdx.x;
    const int w = tid >> 5, lane = tid & 31;
    const int wm = w & 3, wn = w >> 2;
    const int m0 = blockIdx.y << 7, n0 = blockIdx.x * TN;
    const int gid = lane >> 2, tig = lane & 3;

    float acc[2][NT8][4];
#pragma unroll
    for (int mi = 0; mi < 2; ++mi)
#pragma unroll
        for (int nj = 0; nj < NT8; ++nj)
#pragma unroll
            for (int q = 0; q < 4; ++q) acc[mi][nj][q] = 0.f;

    const int a_row = (lane & 7) + ((lane >> 3) & 1) * 8;
    const int a_kh  = (lane >> 4) * 16;
    const int b_row = (lane & 7) + ((lane >> 4) & 1) * 8;
    const int b_kh  = ((lane >> 3) & 1) * 16;

    const unsigned uA = smem_u32(sA), uB = smem_u32(sB);
    const int nslab = K >> 6;
    constexpr int NBF = (TN * 8) / 512;

    auto fillB = [&](int st, int k0) {
#pragma unroll
        for (int ib = 0; ib < NBF; ++ib) {
            int idx = (ib << 9) + tid;
            int r = idx >> 3, k8 = idx & 7;
            unsigned sw = SW128(r * 128 + (k8 << 4));
            size_t go = (size_t)(n0 + r) * ldb + k0 + (k8 << 3);
            cpasync16(uB + st * (2 * BSTG) + sw, &Bh[go]);
            cpasync16(uB + st * (2 * BSTG) + BSTG + sw, &Bl[go]);
        }
        asm volatile("cp.async.commit_group;" ::: "memory");
    };
    auto loadA = [&](int k0, float4* ra) {
        const float* Asrc; int lda, acol;
        if (k0 < K1) { Asrc = A1; lda = lda1; acol = k0; }
        else         { Asrc = A2; lda = lda2; acol = k0 - K1; }
#pragma unroll
        for (int it = 0; it < 4; ++it) {
            int idx = (it << 9) + tid;
            int r = idx >> 4, c4 = idx & 15;
            ra[it] = *(const float4*)&Asrc[(size_t)(m0 + r) * lda + acol + (c4 << 2)];
        }
    };
    auto storeA = [&](int st, const float4* ra) {
#pragma unroll
        for (int it = 0; it < 4; ++it) {
            int idx = (it << 9) + tid;
            int r = idx >> 4, c4 = idx & 15;
            unsigned sw = SW128(r * 128 + (c4 << 3));
            float4 v = ra[it];
            __nv_bfloat16 h0 = __float2bfloat16(v.x);
            __nv_bfloat16 h1 = __float2bfloat16(v.y);
            __nv_bfloat16 h2 = __float2bfloat16(v.z);
            __nv_bfloat16 h3 = __float2bfloat16(v.w);
            __nv_bfloat162 hp0(h0, h1), hp1(h2, h3);
            __nv_bfloat162 lp0(__float2bfloat16(v.x - __bfloat162float(h0)),
                               __float2bfloat16(v.y - __bfloat162float(h1)));
            __nv_bfloat162 lp1(__float2bfloat16(v.z - __bfloat162float(h2)),
                               __float2bfloat16(v.w - __bfloat162float(h3)));
            char* ph = sA + st * 32768 + sw;
            char* pl = sA + st * 32768 + 16384 + sw;
            ((__nv_bfloat162*)ph)[0] = hp0; ((__nv_bfloat162*)ph)[1] = hp1;
            ((__nv_bfloat162*)pl)[0] = lp0; ((__nv_bfloat162*)pl)[1] = lp1;
        }
    };

    {
        float4 ra[4];
        loadA(0, ra);
        storeA(0, ra);
        fillB(0, 0);
        asm volatile("cp.async.wait_group 0;" ::: "memory");
    }
    __syncthreads();

    for (int s = 0; s < nslab; ++s) {
        const int cur = s & 1;
        const bool more = (s + 1 < nslab);
        float4 ra[4];
        if (more) {
            fillB(cur ^ 1, (s + 1) << 6);
            loadA((s + 1) << 6, ra);
        }
        const unsigned uAh = uA + cur * 32768;
        const unsigned uAl = uAh + 16384;
        const unsigned uBh = uB + cur * (2 * BSTG);
        const unsigned uBl = uBh + BSTG;
#pragma unroll
        for (int j = 0; j < 4; ++j) {
            const int kb = j * 32;
            unsigned ah[2][4], al[2][4], bh[NT8][2], bl[NT8][2];
            unsigned aoff = SW128((wm * 32 + a_row) * 128 + kb + a_kh);
            ldsm4(ah[0][0], ah[0][1], ah[0][2], ah[0][3], uAh + aoff);
            ldsm4(ah[1][0], ah[1][1], ah[1][2], ah[1][3], uAh + aoff + 2048);
            ldsm4(al[0][0], al[0][1], al[0][2], al[0][3], uAl + aoff);
            ldsm4(al[1][0], al[1][1], al[1][2], al[1][3], uAl + aoff + 2048);
            unsigned boff = SW128((wn * WN + b_row) * 128 + kb + b_kh);
#pragma unroll
            for (int g = 0; g < NT8 / 2; ++g) {
                ldsm4(bh[2*g][0], bh[2*g][1], bh[2*g+1][0], bh[2*g+1][1],
                      uBh + boff + g * 2048);
                ldsm4(bl[2*g][0], bl[2*g][1], bl[2*g+1][0], bl[2*g+1][1],
                      uBl + boff + g * 2048);
            }
#pragma unroll
            for (int mi = 0; mi < 2; ++mi)
#pragma unroll
                for (int nj = 0; nj < NT8; ++nj)
                    mma16816(acc[mi][nj], ah[mi], bh[nj][0], bh[nj][1]);
#pragma unroll
            for (int mi = 0; mi < 2; ++mi)
#pragma unroll
                for (int nj = 0; nj < NT8; ++nj)
                    mma16816(acc[mi][nj], ah[mi], bl[nj][0], bl[nj][1]);
#pragma unroll
            for (int mi = 0; mi < 2; ++mi)
#pragma unroll
                for (int nj = 0; nj < NT8; ++nj)
                    mma16816(acc[mi][nj], al[mi], bh[nj][0], bh[nj][1]);
        }
        if (more) {
            storeA(cur ^ 1, ra);
            asm volatile("cp.async.wait_group 0;" ::: "memory");
            __syncthreads();
        }
    }

#pragma unroll
    for (int mi = 0; mi < 2; ++mi) {
#pragma unroll
        for (int half = 0; half < 2; ++half) {
            const int row = m0 + wm * 32 + mi * 16 + gid + half * 8;
#pragma unroll
            for (int nj = 0; nj < NT8; ++nj) {
                const int col = n0 + wn * WN + nj * 8 + tig * 2;
                float* cp = &C[(size_t)row * ldc + col];
                float bx = 0.f, by = 0.f;
                if (bias) { float2 bv = *(const float2*)&bias[col]; bx = bv.x; by = bv.y; }
                float v0 = acc[mi][nj][half * 2 + 0] + bx;
                float v1 = acc[mi][nj][half * 2 + 1] + by;
                if (flags & 2) {
                    float2 o = *(const float2*)cp;
                    v0 += o.x; v1 += o.y;
                }
                if (flags & 1) { v0 = fmaxf(v0, 0.f); v1 = fmaxf(v1, 0.f); }
                *(float2*)cp = make_float2(v0, v1);
            }
        }
    }
}

// ============================================================================
// Fused mlp1b + mlp2: one block owns 128 rows; loops the 3 n-tiles (TN=64)
// of hid's rus-part internally, accumulates hid (mlp1a partial), relu -> smem,
// then projects 192 -> 16 experts with w2 and writes logits directly.
// smem: [0,98304) mma pipeline; sH 128x196 f32 @98304; sw2 16x196 f32 @198656.
// ============================================================================
#define FU_SH  98304
#define FU_SW  198656
#define FU_TOT 211200

__global__ void __launch_bounds__(512) k_mma_fused(
    const float* __restrict__ A, int lda,
    const __nv_bfloat16* __restrict__ Bh, const __nv_bfloat16* __restrict__ Bl,
    int ldb,
    const float* __restrict__ hidIn,
    const float* __restrict__ w2, const float* __restrict__ b2,
    float* __restrict__ out)
{
    constexpr int TN = 64, WN = 16, NT8 = 2, BSTG = TN * 128;
    extern __shared__ char smem[];
    char* sA = smem;
    char* sB = smem + 65536;
    float* sH  = (float*)(smem + FU_SH);    // [128][196]
    float* sW2 = (float*)(smem + FU_SW);    // [16][196]

    const int tid = threadIdx.x;
    const int w = tid >> 5, lane = tid & 31;
    const int wm = w & 3, wn = w >> 2;
    const int m0 = blockIdx.x << 7;
    const int gid = lane >> 2, tig = lane & 3;

    // stage w2 (16 x 192) into padded smem
    for (int idx = tid; idx < NX * NMLP; idx += 512) {
        int e = idx / NMLP, k = idx - e * NMLP;
        sW2[e * 196 + k] = w2[idx];
    }

    const int a_row = (lane & 7) + ((lane >> 3) & 1) * 8;
    const int a_kh  = (lane >> 4) * 16;
    const int b_row = (lane & 7) + ((lane >> 4) & 1) * 8;
    const int b_kh  = ((lane >> 3) & 1) * 16;
    const unsigned uA = smem_u32(sA), uB = smem_u32(sB);

    for (int nt = 0; nt < 3; ++nt) {
        const int n0 = nt * TN;
        float acc[2][NT8][4];
#pragma unroll
        for (int mi = 0; mi < 2; ++mi)
#pragma unroll
            for (int nj = 0; nj < NT8; ++nj)
#pragma unroll
                for (int q = 0; q < 4; ++q) acc[mi][nj][q] = 0.f;

        auto fillB = [&](int st, int k0) {
            {
                int idx = tid;   // TN*8/512 = 1
                int r = idx >> 3, k8 = idx & 7;
                unsigned sw = SW128(r * 128 + (k8 << 4));
                size_t go = (size_t)(n0 + r) * ldb + k0 + (k8 << 3);
                cpasync16(uB + st * (2 * BSTG) + sw, &Bh[go]);
                cpasync16(uB + st * (2 * BSTG) + BSTG + sw, &Bl[go]);
            }
            asm volatile("cp.async.commit_group;" ::: "memory");
        };
        auto loadA = [&](int k0, float4* ra) {
#pragma unroll
            for (int it = 0; it < 4; ++it) {
                int idx = (it << 9) + tid;
                int r = idx >> 4, c4 = idx & 15;
                ra[it] = *(const float4*)&A[(size_t)(m0 + r) * lda + k0 + (c4 << 2)];
            }
        };
        auto storeA = [&](int st, const float4* ra) {
#pragma unroll
            for (int it = 0; it < 4; ++it) {
                int idx = (it << 9) + tid;
                int r = idx >> 4, c4 = idx & 15;
                unsigned sw = SW128(r * 128 + (c4 << 3));
                float4 v = ra[it];
                __nv_bfloat16 h0 = __float2bfloat16(v.x);
                __nv_bfloat16 h1 = __float2bfloat16(v.y);
                __nv_bfloat16 h2 = __float2bfloat16(v.z);
                __nv_bfloat16 h3 = __float2bfloat16(v.w);
                __nv_bfloat162 hp0(h0, h1), hp1(h2, h3);
                __nv_bfloat162 lp0(__float2bfloat16(v.x - __bfloat162float(h0)),
                                   __float2bfloat16(v.y - __bfloat162float(h1)));
                __nv_bfloat162 lp1(__float2bfloat16(v.z - __bfloat162float(h2)),
                                   __float2bfloat16(v.w - __bfloat162float(h3)));
                char* ph = sA + st * 32768 + sw;
                char* pl = sA + st * 32768 + 16384 + sw;
                ((__nv_bfloat162*)ph)[0] = hp0; ((__nv_bfloat162*)ph)[1] = hp1;
                ((__nv_bfloat162*)pl)[0] = lp0; ((__nv_bfloat162*)pl)[1] = lp1;
            }
        };

        {
            float4 ra[4];
            loadA(0, ra);
            storeA(0, ra);
            fillB(0, 0);
            asm volatile("cp.async.wait_group 0;" ::: "memory");
        }
        __syncthreads();

        for (int s = 0; s < 2; ++s) {        // K = 128 -> 2 slabs
            const int cur = s & 1;
            const bool more = (s == 0);
            float4 ra[4];
            if (more) {
                fillB(1, 64);
                loadA(64, ra);
            }
            const unsigned uAh = uA + cur * 32768;
            const unsigned uAl = uAh + 16384;
            const unsigned uBh = uB + cur * (2 * BSTG);
            const unsigned uBl = uBh + BSTG;
#pragma unroll
            for (int j = 0; j < 4; ++j) {
                const int kb = j * 32;
                unsigned ah[2][4], al[2][4], bh[NT8][2], bl[NT8][2];
                unsigned aoff = SW128((wm * 32 + a_row) * 128 + kb + a_kh);
                ldsm4(ah[0][0], ah[0][1], ah[0][2], ah[0][3], uAh + aoff);
                ldsm4(ah[1][0], ah[1][1], ah[1][2], ah[1][3], uAh + aoff + 2048);
                ldsm4(al[0][0], al[0][1], al[0][2], al[0][3], uAl + aoff);
                ldsm4(al[1][0], al[1][1], al[1][2], al[1][3], uAl + aoff + 2048);
                unsigned boff = SW128((wn * WN + b_row) * 128 + kb + b_kh);
                ldsm4(bh[0][0], bh[0][1], bh[1][0], bh[1][1], uBh + boff);
                ldsm4(bl[0][0], bl[0][1], bl[1][0], bl[1][1], uBl + boff);
#pragma unroll
                for (int mi = 0; mi < 2; ++mi)
#pragma unroll
                    for (int nj = 0; nj < NT8; ++nj)
                        mma16816(acc[mi][nj], ah[mi], bh[nj][0], bh[nj][1]);
#pragma unroll
                for (int mi = 0; mi < 2; ++mi)
#pragma unroll
                    for (int nj = 0; nj < NT8; ++nj)
                        mma16816(acc[mi][nj], ah[mi], bl[nj][0], bl[nj][1]);
#pragma unroll
                for (int mi = 0; mi < 2; ++mi)
#pragma unroll
                    for (int nj = 0; nj < NT8; ++nj)
                        mma16816(acc[mi][nj], al[mi], bh[nj][0], bh[nj][1]);
            }
            if (more) {
                storeA(1, ra);
                asm volatile("cp.async.wait_group 0;" ::: "memory");
                __syncthreads();
            }
        }

        // epilogue: relu(acc + hid_partial) -> sH
#pragma unroll
        for (int mi = 0; mi < 2; ++mi) {
#pragma unroll
            for (int half = 0; half < 2; ++half) {
                const int rloc = wm * 32 + mi * 16 + gid + half * 8;
                const int row = m0 + rloc;
#pragma unroll
                for (int nj = 0; nj < NT8; ++nj) {
                    const int col = n0 + wn * WN + nj * 8 + tig * 2;
                    float2 o = *(const float2*)&hidIn[(size_t)row * NMLP + col];
                    float v0 = fmaxf(acc[mi][nj][half * 2 + 0] + o.x, 0.f);
                    float v1 = fmaxf(acc[mi][nj][half * 2 + 1] + o.y, 0.f);
                    sH[rloc * 196 + col + 0] = v0;
                    sH[rloc * 196 + col + 1] = v1;
                }
            }
        }
        __syncthreads();
    }

    // final projection: each thread does 4 experts for 1 row (4 threads/row)
    {
        const int rloc = tid >> 2;
        const int e0 = (tid & 3) << 2;
        float acc4[4];
#pragma unroll
        for (int q = 0; q < 4; ++q) acc4[q] = b2[e0 + q];
        const float* hr = &sH[rloc * 196];
        for (int k = 0; k < NMLP; k += 4) {
            float4 hv = *(const float4*)&hr[k];
#pragma unroll
            for (int q = 0; q < 4; ++q) {
                float4 wv = *(const float4*)&sW2[(e0 + q) * 196 + k];
                acc4[q] = fmaf(hv.x, wv.x, acc4[q]);
                acc4[q] = fmaf(hv.y, wv.y, acc4[q]);
                acc4[q] = fmaf(hv.z, wv.z, acc4[q]);
                acc4[q] = fmaf(hv.w, wv.w, acc4[q]);
            }
        }
        *(float4*)&out[(size_t)(m0 + rloc) * NX + e0] =
            make_float4(acc4[0], acc4[1], acc4[2], acc4[3]);
    }
}

// ---------------- per-token attention scalars (Ar, As) ----------------------
__global__ void __launch_bounds__(256) k_scal(const float* __restrict__ R,
                                              const float* __restrict__ S) {
    int warp = (blockIdx.x * blockDim.x + threadIdx.x) >> 5;
    int lane = threadIdx.x & 31;
    if (warp >= NTOK) return;
    int tok = warp;
    const float* pr = g_processed + (size_t)tok * NP;
    float aa = 0.f, ab = 0.f, ac = 0.f;
#pragma unroll
    for (int p = lane; p < NP; p += 32) {
        float pv = pr[p];
        aa = fmaf(pv, g_wa[p], aa);
        ab = fmaf(pv, g_wb[p], ab);
        ac = fmaf(pv, g_wc[p], ac);
    }
#pragma unroll
    for (int o = 16; o; o >>= 1) {
        aa += __shfl_down_sync(0xffffffffu, aa, o);
        ab += __shfl_down_sync(0xffffffffu, ab, o);
        ac += __shfl_down_sync(0xffffffffu, ac, o);
    }
    if (lane == 0) {
        aa += g_cc[0]; ab += g_cc[1]; ac += g_cc[2];
        int t = tok & (NT - 1);
        int s = tok >> 11;          // b*4+m
        int m = s & 3;
        float sc[3], Ro[3], So[3];
        int n = 0;
        for (int j = 0; j < NM; j++) {
            if (j == m) continue;
            size_t idx = ((size_t)s * NM + j) * NT + t;
            float r = R[idx], sv = S[idx];
            Ro[n] = r; So[n] = sv;
            sc[n] = (fmaf(aa, r, fmaf(ab, sv, ac))) * 0.125f;
            n++;
        }
        float mx = fmaxf(sc[0], fmaxf(sc[1], sc[2]));
        float e0 = expf(sc[0] - mx), e1 = expf(sc[1] - mx), e2 = expf(sc[2] - mx);
        float inv = 1.f / (e0 + e1 + e2);
        g_scal[2*tok]   = (e0*Ro[0] + e1*Ro[1] + e2*Ro[2]) * inv;
        g_scal[2*tok+1] = (e0*So[0] + e1*So[1] + e2*So[2]) * inv;
    }
}

// ---------------- GRU scan: one block per sequence (32 blocks) --------------
__global__ void __launch_bounds__(384, 1) k_gru(const float* __restrict__ U,
                                                const float* __restrict__ whh,
                                                const float* __restrict__ bhh) {
    __shared__ __align__(16) float hbuf[NH];
    __shared__ float exch[3*NH];
    __shared__ float exch_xn[NH];
    __shared__ float su[512], sar[512], sas[512];
    const int s = blockIdx.x;
    const int i = threadIdx.x;

    u64 w2r[NH/2];
    const u64* wp = (const u64*)(whh + (size_t)i * NH);
#pragma unroll
    for (int k = 0; k < NH/2; k++) w2r[k] = wp[k];
    const float bb = bhh[i];
    const float c0 = g_c0[i], c1 = g_c1[i], c2 = g_c2[i], c3 = g_c3[i];

    if (i < NH) hbuf[i] = 0.f;
    const size_t base = (size_t)s * NT;
    float* outp = g_rus + base * NH + i;   // valid only for i < NH

    for (int t0 = 0; t0 < NT; t0 += 512) {
        __syncthreads();
        for (int j = i; j < 512; j += 384) {
            size_t g = base + t0 + j;
            su[j]  = U[g];
            sar[j] = g_scal[2*g];
            sas[j] = g_scal[2*g + 1];
        }
        __syncthreads();
        for (int tt = 0; tt < 512; tt++) {
            float xt = fmaf(su[tt], c0, fmaf(sar[tt], c1, fmaf(sas[tt], c2, c3)));
            u64 a0 = 0ull, a1 = 0ull;
#pragma unroll
            for (int k = 0; k < NH/4; k++) {
                ulonglong2 hv = *(const ulonglong2*)&hbuf[k << 2];
                a0 = ffma2(w2r[2*k],   hv.x, a0);
                a1 = ffma2(w2r[2*k+1], hv.y, a1);
            }
            float acc = bb + ((lo2(a0) + hi2(a0)) + (lo2(a1) + hi2(a1)));
            if (i < 2*NH) exch[i] = acc + xt;
            else { exch[i] = acc; exch_xn[i - 2*NH] = xt; }
            __syncthreads();
            if (i < NH) {
                float r = __fdividef(1.f, 1.f + __expf(-exch[i]));
                float z = __fdividef(1.f, 1.f + __expf(-exch[NH + i]));
                float nn = tanhf(fmaf(r, exch[2*NH + i], exch_xn[i]));
                float hnew = fmaf(z, hbuf[i] - nn, nn);   // (1-z)*n + z*h
                outp[(size_t)(t0 + tt) * NH] = hnew;
                hbuf[i] = hnew;
            }
            __syncthreads();
        }
    }
}

// ---------------- launch ----------------------------------------------------
extern "C" void kernel_launch(void* const* d_in, const int* in_sizes, int n_in,
                              void* d_out, int out_size) {
    const float* emb  = (const float*)d_in[0];
    const float* U    = (const float*)d_in[1];
    const float* R    = (const float*)d_in[2];
    const float* S    = (const float*)d_in[3];
    const float* tp_w = (const float*)d_in[4];
    const float* tp_b = (const float*)d_in[5];
    const float* q_w  = (const float*)d_in[6];
    const float* q_b  = (const float*)d_in[7];
    const float* k_w  = (const float*)d_in[8];
    const float* k_b  = (const float*)d_in[9];
    const float* v_w  = (const float*)d_in[10];
    const float* v_b  = (const float*)d_in[11];
    const float* wih  = (const float*)d_in[12];
    const float* whh  = (const float*)d_in[13];
    const float* bih  = (const float*)d_in[14];
    const float* bhh  = (const float*)d_in[15];
    const float* w1   = (const float*)d_in[16];
    const float* b1   = (const float*)d_in[17];
    const float* w2   = (const float*)d_in[18];
    const float* b2   = (const float*)d_in[19];
    float* out = (float*)d_out;

    float *processed, *hid, *rus;
    cudaGetSymbolAddress((void**)&processed, g_processed);
    cudaGetSymbolAddress((void**)&hid, g_hid);
    cudaGetSymbolAddress((void**)&rus, g_rus);
    __nv_bfloat16 *wthi, *wtlo, *w1hi, *w1lo;
    cudaGetSymbolAddress((void**)&wthi, g_wthi);
    cudaGetSymbolAddress((void**)&wtlo, g_wtlo);
    cudaGetSymbolAddress((void**)&w1hi, g_w1hi);
    cudaGetSymbolAddress((void**)&w1lo, g_w1lo);

    const int smem128 = 65536 + 4 * 128 * 128;   // 131072
    const int smem64  = 65536 + 4 * 64 * 128;    // 98304
    cudaFuncSetAttribute(k_mma<128>, cudaFuncAttributeMaxDynamicSharedMemorySize,
                         smem128);
    cudaFuncSetAttribute(k_mma<64>, cudaFuncAttributeMaxDynamicSharedMemorySize,
                         smem64);
    cudaFuncSetAttribute(k_mma_fused, cudaFuncAttributeMaxDynamicSharedMemorySize,
                         FU_TOT);

    // low-priority stream for the overlapped GEMM (GRU must win SM dispatch)
    int prLo = 0, prHi = 0;
    cudaDeviceGetStreamPriorityRange(&prLo, &prHi);
    cudaStream_t s2;
    cudaStreamCreateWithPriority(&s2, cudaStreamNonBlocking, prLo);
    cudaEvent_t ev0, ev1;
    cudaEventCreateWithFlags(&ev0, cudaEventDisableTiming);
    cudaEventCreateWithFlags(&ev1, cudaEventDisableTiming);

    k_pre<<<1, 384>>>(q_w, q_b, k_w, k_b, wih, bih, v_w, v_b);
    k_cvt<<<(NP*NE)/1024, 256>>>(tp_w, wthi, wtlo);
    k_cvt<<<(NMLP*NCOMB)/1024, 256>>>(w1, w1hi, w1lo);
    // processed = relu(emb @ tp_w^T + tp_b)
    k_mma<128><<<dim3(NP/128, NTOK/128), 512, smem128>>>(
        emb, NE, NE, emb, NE, wthi, wtlo, NE, tp_b, processed, NP, NE, 1);
    k_scal<<<NTOK/8, 256>>>(R, S);
    cudaEventRecord(ev0, 0);

    // GRU FIRST (captured before mlp1a -> its 32 blocks get SMs immediately)
    k_gru<<<NB*NM, 384>>>(U, whh, bhh);

    // mlp1a (hid = processed @ w1[:, :256]^T + b1, no relu) on low-prio stream
    cudaStreamWaitEvent(s2, ev0, 0);
    k_mma<64><<<dim3(NMLP/64, NTOK/128), 512, smem64, s2>>>(
        processed, NP, NP, processed, NP, w1hi, w1lo, NCOMB, b1,
        hid, NMLP, NP, 0);
    cudaEventRecord(ev1, s2);

    // Join, then fused: out = relu(hid + rus @ w1[:,256:]^T) @ w2^T + b2
    cudaStreamWaitEvent(0, ev1, 0);
    k_mma_fused<<<NTOK/128, 512, FU_TOT>>>(
        rus, NH, w1hi + NP, w1lo + NP, NCOMB, hid, w2, b2, out);

    cudaEventDestroy(ev0);
    cudaEventDestroy(ev1);
    cudaStreamDestroy(s2);
}